// round 1
// baseline (speedup 1.0000x reference)
#include <cuda_runtime.h>
#include <cuda_bf16.h>
#include <math.h>

// Problem constants
// B=2, S=2048, E=2048, NH=32, NKV=8, HD=64, GROUP=4
// M = B*S = 4096

// -------- scratch (static device globals; allocation-free) --------
__device__ float g_qproj[4096 * 2048];   // x @ Wq   (B*S, E)
__device__ float g_kproj[4096 * 512];    // x @ Wk
__device__ float g_vproj[4096 * 512];    // x @ Wv
__device__ float g_qr[4096 * 2048];      // roped Q in (B,H,S,D)
__device__ float g_attn[4096 * 2048];    // attn out in (B,S,H,D)

// ---------------- SGEMM: C(MxN) = A(MxK) @ B(KxN), all row-major ----------------
// 128x128 tile, BK=8, 256 threads, 8x8 per thread. M,N,K multiples of 128/128/8.
__global__ __launch_bounds__(256) void sgemm_kernel(
    const float* __restrict__ A, const float* __restrict__ B,
    float* __restrict__ C, int M, int N, int K)
{
    __shared__ float As[8][128];
    __shared__ float Bs[8][128];

    const int tid = threadIdx.x;
    const int tr = tid >> 4;        // 0..15
    const int tc = tid & 15;        // 0..15
    const int rowBase = blockIdx.y * 128;
    const int colBase = blockIdx.x * 128;

    const int aRow = tid >> 1;          // 0..127
    const int aK   = (tid & 1) << 2;    // 0 or 4
    const int bRow = tid >> 5;          // 0..7
    const int bCol = (tid & 31) << 2;   // 0..124

    const float* Ap = A + (size_t)(rowBase + aRow) * K + aK;
    const float* Bp = B + (size_t)bRow * N + colBase + bCol;

    float acc[8][8];
#pragma unroll
    for (int i = 0; i < 8; i++)
#pragma unroll
        for (int j = 0; j < 8; j++) acc[i][j] = 0.f;

    for (int k0 = 0; k0 < K; k0 += 8) {
        float4 av = *(const float4*)Ap;
        As[aK + 0][aRow] = av.x;
        As[aK + 1][aRow] = av.y;
        As[aK + 2][aRow] = av.z;
        As[aK + 3][aRow] = av.w;
        float4 bv = *(const float4*)Bp;
        *(float4*)(&Bs[bRow][bCol]) = bv;
        __syncthreads();
#pragma unroll
        for (int kk = 0; kk < 8; kk++) {
            float ar[8], br[8];
#pragma unroll
            for (int i = 0; i < 8; i++) ar[i] = As[kk][tr * 8 + i];
#pragma unroll
            for (int j = 0; j < 8; j++) br[j] = Bs[kk][tc * 8 + j];
#pragma unroll
            for (int i = 0; i < 8; i++)
#pragma unroll
                for (int j = 0; j < 8; j++)
                    acc[i][j] = fmaf(ar[i], br[j], acc[i][j]);
        }
        __syncthreads();
        Ap += 8;
        Bp += (size_t)8 * N;
    }

#pragma unroll
    for (int i = 0; i < 8; i++) {
        float* cp = C + (size_t)(rowBase + tr * 8 + i) * N + colBase + tc * 8;
        *(float4*)cp       = make_float4(acc[i][0], acc[i][1], acc[i][2], acc[i][3]);
        *(float4*)(cp + 4) = make_float4(acc[i][4], acc[i][5], acc[i][6], acc[i][7]);
    }
}

// ---------------- RoPE on Q: (B,S,H,D) proj -> (B,H,S,D) roped ----------------
__global__ __launch_bounds__(256) void rope_q_kernel(
    const float* __restrict__ qp, const float* __restrict__ cosx,
    const float* __restrict__ sinx, float* __restrict__ qo)
{
    int i = blockIdx.x * blockDim.x + threadIdx.x;   // ordered (b,h,s,d)
    int d = i & 63;
    int s = (i >> 6) & 2047;
    int h = (i >> 17) & 31;
    int b = i >> 22;
    size_t src = ((size_t)(b * 2048 + s)) * 2048 + h * 64;
    float v1 = qp[src + d];
    int d2 = (d < 32) ? d + 32 : d - 32;
    float v2 = qp[src + d2];
    float c = cosx[s * 64 + d], sn = sinx[s * 64 + d];
    float rot = (d < 32) ? -v2 : v2;
    qo[i] = v1 * c + rot * sn;   // i == ((b*32+h)*2048+s)*64+d
}

// ---------------- RoPE K + copy V: proj (B,S,KV,D) -> (B,KV,S,D) into d_out ----------------
__global__ __launch_bounds__(256) void rope_kv_kernel(
    const float* __restrict__ kp, const float* __restrict__ vp,
    const float* __restrict__ cosx, const float* __restrict__ sinx,
    float* __restrict__ ko, float* __restrict__ vo)
{
    int i = blockIdx.x * blockDim.x + threadIdx.x;   // ordered (b,kv,s,d)
    int d = i & 63;
    int s = (i >> 6) & 2047;
    int kv = (i >> 17) & 7;
    int b = i >> 20;
    size_t src = ((size_t)(b * 2048 + s)) * 512 + kv * 64;
    float v1 = kp[src + d];
    int d2 = (d < 32) ? d + 32 : d - 32;
    float v2 = kp[src + d2];
    float c = cosx[s * 64 + d], sn = sinx[s * 64 + d];
    ko[i] = v1 * c + ((d < 32) ? -v2 : v2) * sn;     // i == ((b*8+kv)*2048+s)*64+d
    vo[i] = vp[src + d];
}

// ---------------- Flash attention (causal, GQA) ----------------
// 64x64 tiles, 256 threads, 4x4 per thread. Q:(B,H,S,D)  K,V:(B,KV,S,D)
// Output written directly in (B,S,H,D) layout for the Wo GEMM.
__global__ __launch_bounds__(256) void flash_kernel(
    const float* __restrict__ Q, const float* __restrict__ Kg,
    const float* __restrict__ Vg, float* __restrict__ Og)
{
    extern __shared__ float sm[];
    float* Qs = sm;                       // [64][64] row-major (r,d)
    float* Kt = sm + 64 * 64;             // [64][65] (d, c); reused as Pt[c][r]
    float* Vs = sm + 64 * 64 + 64 * 65;   // [64][64] (c, n)

    const int bh = blockIdx.y;            // b*32+h
    const int b = bh >> 5;
    const int h = bh & 31;
    const int kvh = h >> 2;               // GROUP = 4
    const int mTile = blockIdx.x;
    const int tid = threadIdx.x;
    const int ty = tid >> 4, tx = tid & 15;
    const int r0 = ty * 4, c0 = tx * 4;

    const float* qbase = Q + ((size_t)bh * 2048 + mTile * 64) * 64;
    const float* kbase = Kg + ((size_t)(b * 8 + kvh)) * 2048 * 64;
    const float* vbase = Vg + ((size_t)(b * 8 + kvh)) * 2048 * 64;

    for (int i = tid; i < 64 * 64; i += 256) Qs[i] = qbase[i];

    float m_i[4], l_i[4], o[4][4];
#pragma unroll
    for (int i = 0; i < 4; i++) {
        m_i[i] = -1e30f;
        l_i[i] = 0.f;
#pragma unroll
        for (int j = 0; j < 4; j++) o[i][j] = 0.f;
    }

    for (int kn = 0; kn <= mTile; kn++) {
        __syncthreads();   // prev iteration's reads of Kt(P)/Vs done; Qs ready
        const float* kp = kbase + kn * 64 * 64;
        const float* vp = vbase + kn * 64 * 64;
        for (int i = tid; i < 64 * 64; i += 256) {
            int r = i >> 6, d = i & 63;
            Kt[d * 65 + r] = kp[i];
            Vs[i] = vp[i];
        }
        __syncthreads();

        // S = Q @ K^T (4x4 per thread)
        float s4[4][4];
#pragma unroll
        for (int i = 0; i < 4; i++)
#pragma unroll
            for (int j = 0; j < 4; j++) s4[i][j] = 0.f;

        for (int d = 0; d < 64; d++) {
            float qr[4], kr[4];
#pragma unroll
            for (int i = 0; i < 4; i++) qr[i] = Qs[(r0 + i) * 64 + d];
#pragma unroll
            for (int j = 0; j < 4; j++) kr[j] = Kt[d * 65 + c0 + j];
#pragma unroll
            for (int i = 0; i < 4; i++)
#pragma unroll
                for (int j = 0; j < 4; j++)
                    s4[i][j] = fmaf(qr[i], kr[j], s4[i][j]);
        }

        // scale + causal mask
        const int rg0 = mTile * 64 + r0;
        const int cg0 = kn * 64 + c0;
#pragma unroll
        for (int i = 0; i < 4; i++)
#pragma unroll
            for (int j = 0; j < 4; j++) {
                s4[i][j] *= 0.125f;
                if (cg0 + j > rg0 + i) s4[i][j] = -1e30f;
            }

        // online softmax: each row owned by a 16-lane group (same ty)
#pragma unroll
        for (int i = 0; i < 4; i++) {
            float tmax = fmaxf(fmaxf(s4[i][0], s4[i][1]), fmaxf(s4[i][2], s4[i][3]));
#pragma unroll
            for (int off = 8; off >= 1; off >>= 1)
                tmax = fmaxf(tmax, __shfl_xor_sync(0xffffffffu, tmax, off));
            float mnew = fmaxf(m_i[i], tmax);
            float fac = __expf(m_i[i] - mnew);
            float psum = 0.f;
#pragma unroll
            for (int j = 0; j < 4; j++) {
                s4[i][j] = __expf(s4[i][j] - mnew);
                psum += s4[i][j];
            }
#pragma unroll
            for (int off = 8; off >= 1; off >>= 1)
                psum += __shfl_xor_sync(0xffffffffu, psum, off);
            l_i[i] = l_i[i] * fac + psum;
            m_i[i] = mnew;
#pragma unroll
            for (int j = 0; j < 4; j++) o[i][j] *= fac;
        }

        __syncthreads();   // all threads done reading Kt (K data)
        // store P transposed into Kt: Pt[c][r]
#pragma unroll
        for (int i = 0; i < 4; i++)
#pragma unroll
            for (int j = 0; j < 4; j++)
                Kt[(c0 + j) * 65 + r0 + i] = s4[i][j];
        __syncthreads();

        // O += P @ V
        for (int c = 0; c < 64; c++) {
            float pr[4], vr[4];
#pragma unroll
            for (int i = 0; i < 4; i++) pr[i] = Kt[c * 65 + r0 + i];
#pragma unroll
            for (int j = 0; j < 4; j++) vr[j] = Vs[c * 64 + c0 + j];
#pragma unroll
            for (int i = 0; i < 4; i++)
#pragma unroll
                for (int j = 0; j < 4; j++)
                    o[i][j] = fmaf(pr[i], vr[j], o[i][j]);
        }
    }

    // epilogue: write (b, s, h, d)
#pragma unroll
    for (int i = 0; i < 4; i++) {
        float inv = 1.f / l_i[i];
        size_t row = (size_t)(b * 2048 + mTile * 64 + r0 + i) * 2048 + h * 64 + c0;
#pragma unroll
        for (int j = 0; j < 4; j++) Og[row + j] = o[i][j] * inv;
    }
}

extern "C" void kernel_launch(void* const* d_in, const int* in_sizes, int n_in,
                              void* d_out, int out_size)
{
    const float* x    = (const float*)d_in[0];
    // d_in[1] = mask (deterministic causal triu) — computed analytically, not read
    const float* cosx = (const float*)d_in[2];
    const float* sinx = (const float*)d_in[3];
    const float* Wq   = (const float*)d_in[4];
    const float* Wk   = (const float*)d_in[5];
    const float* Wv   = (const float*)d_in[6];
    const float* Wo   = (const float*)d_in[7];

    float* out  = (float*)d_out;          // (B,S,E)      8388608
    float* outK = out + 8388608;          // (B,KV,S,D)   2097152
    float* outV = outK + 2097152;         // (B,KV,S,D)   2097152

    float *qproj, *kproj, *vproj, *qr, *attn;
    cudaGetSymbolAddress((void**)&qproj, g_qproj);
    cudaGetSymbolAddress((void**)&kproj, g_kproj);
    cudaGetSymbolAddress((void**)&vproj, g_vproj);
    cudaGetSymbolAddress((void**)&qr,    g_qr);
    cudaGetSymbolAddress((void**)&attn,  g_attn);

    const int FLASH_SMEM = (64 * 64 + 64 * 65 + 64 * 64) * 4;   // 49408 B
    cudaFuncSetAttribute(flash_kernel,
                         cudaFuncAttributeMaxDynamicSharedMemorySize, FLASH_SMEM);

    dim3 blk(256);
    // Projections
    sgemm_kernel<<<dim3(16, 32), blk>>>(x, Wq, qproj, 4096, 2048, 2048);
    sgemm_kernel<<<dim3(4, 32),  blk>>>(x, Wk, kproj, 4096, 512, 2048);
    sgemm_kernel<<<dim3(4, 32),  blk>>>(x, Wv, vproj, 4096, 512, 2048);
    // RoPE + layout transforms (K/V go straight into d_out)
    rope_q_kernel<<<8388608 / 256, 256>>>(qproj, cosx, sinx, qr);
    rope_kv_kernel<<<2097152 / 256, 256>>>(kproj, vproj, cosx, sinx, outK, outV);
    // Attention (reads K/V from d_out regions)
    flash_kernel<<<dim3(32, 64), blk, FLASH_SMEM>>>(qr, outK, outV, attn);
    // Output projection
    sgemm_kernel<<<dim3(16, 32), blk>>>(attn, Wo, out, 4096, 2048, 2048);
}

// round 5
// speedup vs baseline: 1.8977x; 1.8977x over previous
#include <cuda_runtime.h>
#include <cuda_bf16.h>
#include <math.h>
#include <stdint.h>

// Problem constants: B=2, S=2048, E=2048, NH=32, NKV=8, HD=64, GROUP=4, M=B*S=4096

// -------- scratch (static device globals; allocation-free) --------
__device__ float g_qproj[4096 * 2048];
__device__ float g_kproj[4096 * 512];
__device__ float g_vproj[4096 * 512];
__device__ float g_qr[4096 * 2048];      // roped Q in (B,H,S,D)
__device__ float g_attn[4096 * 2048];    // attn out in (B,S,H,D)

// bf16 split operands
__device__ __nv_bfloat16 g_xhi[4096 * 2048];
__device__ __nv_bfloat16 g_xlo[4096 * 2048];
__device__ __nv_bfloat16 g_ahi[4096 * 2048];
__device__ __nv_bfloat16 g_alo[4096 * 2048];
__device__ __nv_bfloat16 g_wqt_hi[2048 * 2048];
__device__ __nv_bfloat16 g_wqt_lo[2048 * 2048];
__device__ __nv_bfloat16 g_wkt_hi[512 * 2048];
__device__ __nv_bfloat16 g_wkt_lo[512 * 2048];
__device__ __nv_bfloat16 g_wvt_hi[512 * 2048];
__device__ __nv_bfloat16 g_wvt_lo[512 * 2048];
__device__ __nv_bfloat16 g_wot_hi[2048 * 2048];
__device__ __nv_bfloat16 g_wot_lo[2048 * 2048];

// ================= PTX helpers (compute_103-safe: no tcgen05) =================
__device__ __forceinline__ uint32_t smem_u32(const void* p) {
    uint32_t a;
    asm("{ .reg .u64 t; cvta.to.shared.u64 t, %1; cvt.u32.u64 %0, t; }" : "=r"(a) : "l"(p));
    return a;
}
__device__ __forceinline__ void cp_async16(uint32_t dst, const void* src) {
    asm volatile("cp.async.cg.shared.global [%0], [%1], 16;" :: "r"(dst), "l"(src));
}
#define CP_COMMIT() asm volatile("cp.async.commit_group;" ::: "memory")
#define CP_WAIT(n)  asm volatile("cp.async.wait_group %0;" :: "n"(n) : "memory")

__device__ __forceinline__ void ldm_x4(uint32_t* r, uint32_t addr) {
    asm volatile("ldmatrix.sync.aligned.m8n8.x4.shared.b16 {%0,%1,%2,%3}, [%4];"
                 : "=r"(r[0]), "=r"(r[1]), "=r"(r[2]), "=r"(r[3]) : "r"(addr));
}
__device__ __forceinline__ void ldm_x2(uint32_t* r, uint32_t addr) {
    asm volatile("ldmatrix.sync.aligned.m8n8.x2.shared.b16 {%0,%1}, [%2];"
                 : "=r"(r[0]), "=r"(r[1]) : "r"(addr));
}
__device__ __forceinline__ void mma_bf16(float* c, const uint32_t* a, const uint32_t* b) {
    asm volatile(
        "mma.sync.aligned.m16n8k16.row.col.f32.bf16.bf16.f32 "
        "{%0,%1,%2,%3}, {%4,%5,%6,%7}, {%8,%9}, {%0,%1,%2,%3};"
        : "+f"(c[0]), "+f"(c[1]), "+f"(c[2]), "+f"(c[3])
        : "r"(a[0]), "r"(a[1]), "r"(a[2]), "r"(a[3]), "r"(b[0]), "r"(b[1]));
}

// ================= elementwise split fp32 -> bf16 hi/lo =================
__global__ __launch_bounds__(256) void split_kernel(
    const float* __restrict__ src, __nv_bfloat16* __restrict__ hi,
    __nv_bfloat16* __restrict__ lo)
{
    int i = blockIdx.x * 256 + threadIdx.x;
    float v = src[i];
    __nv_bfloat16 h = __float2bfloat16(v);
    hi[i] = h;
    lo[i] = __float2bfloat16(v - __bfloat162float(h));
}

// ============ weight transpose + split: W(K x N) -> WT_hi/lo (N x K) ============
__global__ __launch_bounds__(256) void transpose_split_kernel(
    const float* __restrict__ W, __nv_bfloat16* __restrict__ hi,
    __nv_bfloat16* __restrict__ lo, int K, int N)
{
    __shared__ float t[32][33];
    int n0 = blockIdx.x * 32, k0 = blockIdx.y * 32;
    int tx = threadIdx.x, ty = threadIdx.y;   // 32 x 8
#pragma unroll
    for (int i = 0; i < 32; i += 8)
        t[ty + i][tx] = W[(size_t)(k0 + ty + i) * N + n0 + tx];
    __syncthreads();
#pragma unroll
    for (int i = 0; i < 32; i += 8) {
        float v = t[tx][ty + i];
        __nv_bfloat16 h = __float2bfloat16(v);
        size_t o = (size_t)(n0 + ty + i) * K + k0 + tx;
        hi[o] = h;
        lo[o] = __float2bfloat16(v - __bfloat162float(h));
    }
}

// ================= mma.sync split-bf16 GEMM =================
// C(MxN) fp32 = A(MxK) @ B^T  with A hi/lo (M,K) and B hi/lo (N,K), K-major.
// CTA tile 128x128, BK=32, double-buffered cp.async. 256 threads = 8 warps (2m x 4n),
// warp tile 64x32, mma.m16n8k16: 4 m-tiles x 4 n-tiles, 3 products (hh, hl, lh).
//
// Smem tile layout: rows of 32 bf16 padded to 40 (80B stride):
//   80*r mod 128 = {0,80,32,112,64,16,96,48} -> conflict-free ldmatrix & cp.async.
static const int TILE_B = 128 * 40 * 2;          // 10240 B per operand tile
static const int BUF_B  = 4 * TILE_B;            // Ahi,Alo,Bhi,Blo = 40960 B
static const int GEMM_SMEM = 2 * BUF_B;          // 81920 B

__device__ __forceinline__ void load_chunk(
    const __nv_bfloat16* __restrict__ Ahi, const __nv_bfloat16* __restrict__ Alo,
    const __nv_bfloat16* __restrict__ Bhi, const __nv_bfloat16* __restrict__ Blo,
    int m0, int n0, int k0, int K, uint32_t smbuf, int tid)
{
#pragma unroll
    for (int t = 0; t < 4; t++) {
        const __nv_bfloat16* src =
            (t == 0) ? Ahi + (size_t)m0 * K + k0 :
            (t == 1) ? Alo + (size_t)m0 * K + k0 :
            (t == 2) ? Bhi + (size_t)n0 * K + k0 :
                       Blo + (size_t)n0 * K + k0;
        uint32_t dstb = smbuf + t * TILE_B;
#pragma unroll
        for (int v = 0; v < 2; v++) {
            int idx = v * 256 + tid;             // 512 16B vectors per tile
            int row = idx >> 2, col16 = idx & 3;
            cp_async16(dstb + row * 80 + col16 * 16,
                       src + (size_t)row * K + col16 * 8);
        }
    }
}

__global__ __launch_bounds__(256, 1) void gemm_mma_kernel(
    const __nv_bfloat16* __restrict__ Ahi, const __nv_bfloat16* __restrict__ Alo,
    const __nv_bfloat16* __restrict__ Bhi, const __nv_bfloat16* __restrict__ Blo,
    float* __restrict__ C, int M, int N, int K)
{
    extern __shared__ char sm[];
    uint32_t smb = smem_u32(sm);
    const int tid = threadIdx.x;
    const int lane = tid & 31, wid = tid >> 5;
    const int warp_m = wid >> 2;                 // 0..1  -> m offset *64
    const int warp_n = wid & 3;                  // 0..3  -> n offset *32
    const int m0 = blockIdx.y * 128, n0 = blockIdx.x * 128;

    float acc[4][4][4];
#pragma unroll
    for (int i = 0; i < 4; i++)
#pragma unroll
        for (int j = 0; j < 4; j++)
#pragma unroll
            for (int r = 0; r < 4; r++) acc[i][j][r] = 0.f;

    const int nc = K >> 5;                       // BK=32
    load_chunk(Ahi, Alo, Bhi, Blo, m0, n0, 0, K, smb, tid);
    CP_COMMIT();

    // per-lane ldmatrix address components (element offsets within a tile row)
    const int a_row = warp_m * 64 + (lane & 15);           // + mt*16
    const int a_colb = ((lane >> 4) << 3) * 2;             // byte offset for k-half
    const int b_row = warp_n * 32 + (lane & 7);            // + nt*8
    const int b_colb = (((lane >> 3) & 1) << 3) * 2;

    for (int c = 0; c < nc; c++) {
        uint32_t buf = smb + (c & 1) * BUF_B;
        if (c + 1 < nc) {
            load_chunk(Ahi, Alo, Bhi, Blo, m0, n0, (c + 1) << 5, K,
                       smb + ((c + 1) & 1) * BUF_B, tid);
            CP_COMMIT();
            CP_WAIT(1);
        } else {
            CP_WAIT(0);
        }
        __syncthreads();

#pragma unroll
        for (int ks = 0; ks < 2; ks++) {         // two k16 steps in BK=32
            const int ksb = ks * 32;             // 16 elem * 2B
            uint32_t ah[4][4], al[4][4], bh[4][2], bl[4][2];
#pragma unroll
            for (int mt = 0; mt < 4; mt++) {
                uint32_t rowoff = (uint32_t)(a_row + mt * 16) * 80 + ksb + a_colb;
                ldm_x4(ah[mt], buf + 0 * TILE_B + rowoff);
                ldm_x4(al[mt], buf + 1 * TILE_B + rowoff);
            }
#pragma unroll
            for (int nt = 0; nt < 4; nt++) {
                uint32_t rowoff = (uint32_t)(b_row + nt * 8) * 80 + ksb + b_colb;
                ldm_x2(bh[nt], buf + 2 * TILE_B + rowoff);
                ldm_x2(bl[nt], buf + 3 * TILE_B + rowoff);
            }
#pragma unroll
            for (int mt = 0; mt < 4; mt++)
#pragma unroll
                for (int nt = 0; nt < 4; nt++) {
                    mma_bf16(acc[mt][nt], ah[mt], bh[nt]);
                    mma_bf16(acc[mt][nt], ah[mt], bl[nt]);
                    mma_bf16(acc[mt][nt], al[mt], bh[nt]);
                }
        }
        __syncthreads();
    }

    // writeback: thread holds (m = t/4 [+8], n = 2*(t%4) [+1]) per mma tile
    const int cm = lane >> 2, cn = (lane & 3) << 1;
#pragma unroll
    for (int mt = 0; mt < 4; mt++) {
        int gm = m0 + warp_m * 64 + mt * 16 + cm;
#pragma unroll
        for (int nt = 0; nt < 4; nt++) {
            int gn = n0 + warp_n * 32 + nt * 8 + cn;
            float* cp0 = C + (size_t)gm * N + gn;
            cp0[0] = acc[mt][nt][0];
            cp0[1] = acc[mt][nt][1];
            float* cp1 = C + (size_t)(gm + 8) * N + gn;
            cp1[0] = acc[mt][nt][2];
            cp1[1] = acc[mt][nt][3];
        }
    }
}

// ---------------- RoPE on Q: (B,S,H,D) proj -> (B,H,S,D) roped ----------------
__global__ __launch_bounds__(256) void rope_q_kernel(
    const float* __restrict__ qp, const float* __restrict__ cosx,
    const float* __restrict__ sinx, float* __restrict__ qo)
{
    int i = blockIdx.x * blockDim.x + threadIdx.x;
    int d = i & 63;
    int s = (i >> 6) & 2047;
    int h = (i >> 17) & 31;
    int b = i >> 22;
    size_t src = ((size_t)(b * 2048 + s)) * 2048 + h * 64;
    float v1 = qp[src + d];
    int d2 = (d < 32) ? d + 32 : d - 32;
    float v2 = qp[src + d2];
    float c = cosx[s * 64 + d], sn = sinx[s * 64 + d];
    float rot = (d < 32) ? -v2 : v2;
    qo[i] = v1 * c + rot * sn;
}

// ------------- RoPE K + copy V: proj (B,S,KV,D) -> (B,KV,S,D) into d_out -------------
__global__ __launch_bounds__(256) void rope_kv_kernel(
    const float* __restrict__ kp, const float* __restrict__ vp,
    const float* __restrict__ cosx, const float* __restrict__ sinx,
    float* __restrict__ ko, float* __restrict__ vo)
{
    int i = blockIdx.x * blockDim.x + threadIdx.x;
    int d = i & 63;
    int s = (i >> 6) & 2047;
    int kv = (i >> 17) & 7;
    int b = i >> 20;
    size_t src = ((size_t)(b * 2048 + s)) * 512 + kv * 64;
    float v1 = kp[src + d];
    int d2 = (d < 32) ? d + 32 : d - 32;
    float v2 = kp[src + d2];
    float c = cosx[s * 64 + d], sn = sinx[s * 64 + d];
    ko[i] = v1 * c + ((d < 32) ? -v2 : v2) * sn;
    vo[i] = vp[src + d];
}

// ---------------- Flash attention (causal, GQA), fp32 ----------------
__global__ __launch_bounds__(256) void flash_kernel(
    const float* __restrict__ Q, const float* __restrict__ Kg,
    const float* __restrict__ Vg, float* __restrict__ Og)
{
    extern __shared__ float smf[];
    float* Qs = smf;
    float* Kt = smf + 64 * 64;
    float* Vs = smf + 64 * 64 + 64 * 65;

    const int bh = blockIdx.y;
    const int b = bh >> 5;
    const int h = bh & 31;
    const int kvh = h >> 2;
    const int mTile = blockIdx.x;
    const int tid = threadIdx.x;
    const int ty = tid >> 4, tx = tid & 15;
    const int r0 = ty * 4, c0 = tx * 4;

    const float* qbase = Q + ((size_t)bh * 2048 + mTile * 64) * 64;
    const float* kbase = Kg + ((size_t)(b * 8 + kvh)) * 2048 * 64;
    const float* vbase = Vg + ((size_t)(b * 8 + kvh)) * 2048 * 64;

    for (int i = tid; i < 64 * 64; i += 256) Qs[i] = qbase[i];

    float m_i[4], l_i[4], o[4][4];
#pragma unroll
    for (int i = 0; i < 4; i++) {
        m_i[i] = -1e30f; l_i[i] = 0.f;
#pragma unroll
        for (int j = 0; j < 4; j++) o[i][j] = 0.f;
    }

    for (int kn = 0; kn <= mTile; kn++) {
        __syncthreads();
        const float* kp = kbase + kn * 64 * 64;
        const float* vp = vbase + kn * 64 * 64;
        for (int i = tid; i < 64 * 64; i += 256) {
            int r = i >> 6, d = i & 63;
            Kt[d * 65 + r] = kp[i];
            Vs[i] = vp[i];
        }
        __syncthreads();

        float s4[4][4];
#pragma unroll
        for (int i = 0; i < 4; i++)
#pragma unroll
            for (int j = 0; j < 4; j++) s4[i][j] = 0.f;

        for (int d = 0; d < 64; d++) {
            float qr[4], kr[4];
#pragma unroll
            for (int i = 0; i < 4; i++) qr[i] = Qs[(r0 + i) * 64 + d];
#pragma unroll
            for (int j = 0; j < 4; j++) kr[j] = Kt[d * 65 + c0 + j];
#pragma unroll
            for (int i = 0; i < 4; i++)
#pragma unroll
                for (int j = 0; j < 4; j++)
                    s4[i][j] = fmaf(qr[i], kr[j], s4[i][j]);
        }

        const int rg0 = mTile * 64 + r0;
        const int cg0 = kn * 64 + c0;
#pragma unroll
        for (int i = 0; i < 4; i++)
#pragma unroll
            for (int j = 0; j < 4; j++) {
                s4[i][j] *= 0.125f;
                if (cg0 + j > rg0 + i) s4[i][j] = -1e30f;
            }

#pragma unroll
        for (int i = 0; i < 4; i++) {
            float tmax = fmaxf(fmaxf(s4[i][0], s4[i][1]), fmaxf(s4[i][2], s4[i][3]));
#pragma unroll
            for (int off = 8; off >= 1; off >>= 1)
                tmax = fmaxf(tmax, __shfl_xor_sync(0xffffffffu, tmax, off));
            float mnew = fmaxf(m_i[i], tmax);
            float fac = __expf(m_i[i] - mnew);
            float psum = 0.f;
#pragma unroll
            for (int j = 0; j < 4; j++) {
                s4[i][j] = __expf(s4[i][j] - mnew);
                psum += s4[i][j];
            }
#pragma unroll
            for (int off = 8; off >= 1; off >>= 1)
                psum += __shfl_xor_sync(0xffffffffu, psum, off);
            l_i[i] = l_i[i] * fac + psum;
            m_i[i] = mnew;
#pragma unroll
            for (int j = 0; j < 4; j++) o[i][j] *= fac;
        }

        __syncthreads();
#pragma unroll
        for (int i = 0; i < 4; i++)
#pragma unroll
            for (int j = 0; j < 4; j++)
                Kt[(c0 + j) * 65 + r0 + i] = s4[i][j];
        __syncthreads();

        for (int c = 0; c < 64; c++) {
            float pr[4], vr[4];
#pragma unroll
            for (int i = 0; i < 4; i++) pr[i] = Kt[c * 65 + r0 + i];
#pragma unroll
            for (int j = 0; j < 4; j++) vr[j] = Vs[c * 64 + c0 + j];
#pragma unroll
            for (int i = 0; i < 4; i++)
#pragma unroll
                for (int j = 0; j < 4; j++)
                    o[i][j] = fmaf(pr[i], vr[j], o[i][j]);
        }
    }

#pragma unroll
    for (int i = 0; i < 4; i++) {
        float inv = 1.f / l_i[i];
        size_t row = (size_t)(b * 2048 + mTile * 64 + r0 + i) * 2048 + h * 64 + c0;
#pragma unroll
        for (int j = 0; j < 4; j++) Og[row + j] = o[i][j] * inv;
    }
}

extern "C" void kernel_launch(void* const* d_in, const int* in_sizes, int n_in,
                              void* d_out, int out_size)
{
    const float* x    = (const float*)d_in[0];
    // d_in[1] = mask (deterministic causal triu) — computed analytically
    const float* cosx = (const float*)d_in[2];
    const float* sinx = (const float*)d_in[3];
    const float* Wq   = (const float*)d_in[4];
    const float* Wk   = (const float*)d_in[5];
    const float* Wv   = (const float*)d_in[6];
    const float* Wo   = (const float*)d_in[7];

    float* out  = (float*)d_out;          // (B,S,E)
    float* outK = out + 8388608;          // (B,KV,S,D)
    float* outV = outK + 2097152;

    float *qproj, *kproj, *vproj, *qr, *attn;
    cudaGetSymbolAddress((void**)&qproj, g_qproj);
    cudaGetSymbolAddress((void**)&kproj, g_kproj);
    cudaGetSymbolAddress((void**)&vproj, g_vproj);
    cudaGetSymbolAddress((void**)&qr,    g_qr);
    cudaGetSymbolAddress((void**)&attn,  g_attn);

    __nv_bfloat16 *xhi, *xlo, *ahi, *alo;
    __nv_bfloat16 *wqh, *wql, *wkh, *wkl, *wvh, *wvl, *woh, *wol;
    cudaGetSymbolAddress((void**)&xhi, g_xhi);
    cudaGetSymbolAddress((void**)&xlo, g_xlo);
    cudaGetSymbolAddress((void**)&ahi, g_ahi);
    cudaGetSymbolAddress((void**)&alo, g_alo);
    cudaGetSymbolAddress((void**)&wqh, g_wqt_hi);
    cudaGetSymbolAddress((void**)&wql, g_wqt_lo);
    cudaGetSymbolAddress((void**)&wkh, g_wkt_hi);
    cudaGetSymbolAddress((void**)&wkl, g_wkt_lo);
    cudaGetSymbolAddress((void**)&wvh, g_wvt_hi);
    cudaGetSymbolAddress((void**)&wvl, g_wvt_lo);
    cudaGetSymbolAddress((void**)&woh, g_wot_hi);
    cudaGetSymbolAddress((void**)&wol, g_wot_lo);

    cudaFuncSetAttribute(gemm_mma_kernel,
                         cudaFuncAttributeMaxDynamicSharedMemorySize, GEMM_SMEM);
    const int FLASH_SMEM = (64 * 64 + 64 * 65 + 64 * 64) * 4;
    cudaFuncSetAttribute(flash_kernel,
                         cudaFuncAttributeMaxDynamicSharedMemorySize, FLASH_SMEM);

    dim3 blk(256);
    dim3 tblk(32, 8);

    // Preprocess: split x; transpose+split weights
    split_kernel<<<8388608 / 256, blk>>>(x, xhi, xlo);
    transpose_split_kernel<<<dim3(64, 64), tblk>>>(Wq, wqh, wql, 2048, 2048);
    transpose_split_kernel<<<dim3(16, 64), tblk>>>(Wk, wkh, wkl, 2048, 512);
    transpose_split_kernel<<<dim3(16, 64), tblk>>>(Wv, wvh, wvl, 2048, 512);
    transpose_split_kernel<<<dim3(64, 64), tblk>>>(Wo, woh, wol, 2048, 2048);

    // Projections on tensor cores (mma.sync bf16, split-precision)
    gemm_mma_kernel<<<dim3(16, 32), blk, GEMM_SMEM>>>(xhi, xlo, wqh, wql, qproj, 4096, 2048, 2048);
    gemm_mma_kernel<<<dim3(4, 32),  blk, GEMM_SMEM>>>(xhi, xlo, wkh, wkl, kproj, 4096, 512, 2048);
    gemm_mma_kernel<<<dim3(4, 32),  blk, GEMM_SMEM>>>(xhi, xlo, wvh, wvl, vproj, 4096, 512, 2048);

    // RoPE + layout transforms (K/V straight into d_out)
    rope_q_kernel<<<8388608 / 256, 256>>>(qproj, cosx, sinx, qr);
    rope_kv_kernel<<<2097152 / 256, 256>>>(kproj, vproj, cosx, sinx, outK, outV);

    // Attention (fp32, reads K/V from d_out)
    flash_kernel<<<dim3(32, 64), blk, FLASH_SMEM>>>(qr, outK, outV, attn);

    // Output projection
    split_kernel<<<8388608 / 256, blk>>>(attn, ahi, alo);
    gemm_mma_kernel<<<dim3(16, 32), blk, GEMM_SMEM>>>(ahi, alo, woh, wol, out, 4096, 2048, 2048);
}

// round 6
// speedup vs baseline: 3.0308x; 1.5971x over previous
#include <cuda_runtime.h>
#include <cuda_bf16.h>
#include <math.h>
#include <stdint.h>

// Problem constants: B=2, S=2048, E=2048, NH=32, NKV=8, HD=64, GROUP=4, M=B*S=4096

// -------- scratch (static device globals; allocation-free) --------
__device__ float g_qproj[4096 * 2048];
__device__ float g_kproj[4096 * 512];
__device__ float g_vproj[4096 * 512];

__device__ __nv_bfloat16 g_qrh[4096 * 2048];   // roped Q hi (B,H,S,D)
__device__ __nv_bfloat16 g_qrl[4096 * 2048];   // roped Q lo
__device__ __nv_bfloat16 g_khi[2097152];       // roped K hi (B,KV,S,D)
__device__ __nv_bfloat16 g_klo[2097152];
__device__ __nv_bfloat16 g_vhi[2097152];
__device__ __nv_bfloat16 g_vlo[2097152];

__device__ __nv_bfloat16 g_xhi[4096 * 2048];
__device__ __nv_bfloat16 g_xlo[4096 * 2048];
__device__ __nv_bfloat16 g_ahi[4096 * 2048];   // attn out hi (B,S,H,D)
__device__ __nv_bfloat16 g_alo[4096 * 2048];
__device__ __nv_bfloat16 g_wqt_hi[2048 * 2048];
__device__ __nv_bfloat16 g_wqt_lo[2048 * 2048];
__device__ __nv_bfloat16 g_wkt_hi[512 * 2048];
__device__ __nv_bfloat16 g_wkt_lo[512 * 2048];
__device__ __nv_bfloat16 g_wvt_hi[512 * 2048];
__device__ __nv_bfloat16 g_wvt_lo[512 * 2048];
__device__ __nv_bfloat16 g_wot_hi[2048 * 2048];
__device__ __nv_bfloat16 g_wot_lo[2048 * 2048];

// ================= PTX helpers (compute_103-safe) =================
__device__ __forceinline__ uint32_t smem_u32(const void* p) {
    uint32_t a;
    asm("{ .reg .u64 t; cvta.to.shared.u64 t, %1; cvt.u32.u64 %0, t; }" : "=r"(a) : "l"(p));
    return a;
}
__device__ __forceinline__ void cp_async16(uint32_t dst, const void* src) {
    asm volatile("cp.async.cg.shared.global [%0], [%1], 16;" :: "r"(dst), "l"(src));
}
#define CP_COMMIT() asm volatile("cp.async.commit_group;" ::: "memory")
#define CP_WAIT(n)  asm volatile("cp.async.wait_group %0;" :: "n"(n) : "memory")

__device__ __forceinline__ void ldm_x4(uint32_t* r, uint32_t addr) {
    asm volatile("ldmatrix.sync.aligned.m8n8.x4.shared.b16 {%0,%1,%2,%3}, [%4];"
                 : "=r"(r[0]), "=r"(r[1]), "=r"(r[2]), "=r"(r[3]) : "r"(addr));
}
__device__ __forceinline__ void ldm_x2(uint32_t* r, uint32_t addr) {
    asm volatile("ldmatrix.sync.aligned.m8n8.x2.shared.b16 {%0,%1}, [%2];"
                 : "=r"(r[0]), "=r"(r[1]) : "r"(addr));
}
__device__ __forceinline__ void ldm_x2t(uint32_t* r, uint32_t addr) {
    asm volatile("ldmatrix.sync.aligned.m8n8.x2.trans.shared.b16 {%0,%1}, [%2];"
                 : "=r"(r[0]), "=r"(r[1]) : "r"(addr));
}
__device__ __forceinline__ void mma_bf16(float* c, const uint32_t* a, const uint32_t* b) {
    asm volatile(
        "mma.sync.aligned.m16n8k16.row.col.f32.bf16.bf16.f32 "
        "{%0,%1,%2,%3}, {%4,%5,%6,%7}, {%8,%9}, {%0,%1,%2,%3};"
        : "+f"(c[0]), "+f"(c[1]), "+f"(c[2]), "+f"(c[3])
        : "r"(a[0]), "r"(a[1]), "r"(a[2]), "r"(a[3]), "r"(b[0]), "r"(b[1]));
}
// pack two fp32 into bf16x2: lo -> low half, hi -> high half (rn rounding)
__device__ __forceinline__ uint32_t pack_bf16(float lo, float hi) {
    uint32_t r;
    asm("cvt.rn.bf16x2.f32 %0, %1, %2;" : "=r"(r) : "f"(hi), "f"(lo));
    return r;
}

// ================= elementwise split fp32 -> bf16 hi/lo =================
__global__ __launch_bounds__(256) void split_kernel(
    const float* __restrict__ src, __nv_bfloat16* __restrict__ hi,
    __nv_bfloat16* __restrict__ lo)
{
    int i = blockIdx.x * 256 + threadIdx.x;
    float v = src[i];
    __nv_bfloat16 h = __float2bfloat16(v);
    hi[i] = h;
    lo[i] = __float2bfloat16(v - __bfloat162float(h));
}

// ============ weight transpose + split: W(K x N) -> WT_hi/lo (N x K) ============
__global__ __launch_bounds__(256) void transpose_split_kernel(
    const float* __restrict__ W, __nv_bfloat16* __restrict__ hi,
    __nv_bfloat16* __restrict__ lo, int K, int N)
{
    __shared__ float t[32][33];
    int n0 = blockIdx.x * 32, k0 = blockIdx.y * 32;
    int tx = threadIdx.x, ty = threadIdx.y;   // 32 x 8
#pragma unroll
    for (int i = 0; i < 32; i += 8)
        t[ty + i][tx] = W[(size_t)(k0 + ty + i) * N + n0 + tx];
    __syncthreads();
#pragma unroll
    for (int i = 0; i < 32; i += 8) {
        float v = t[tx][ty + i];
        __nv_bfloat16 h = __float2bfloat16(v);
        size_t o = (size_t)(n0 + ty + i) * K + k0 + tx;
        hi[o] = h;
        lo[o] = __float2bfloat16(v - __bfloat162float(h));
    }
}

// ================= mma.sync split-bf16 GEMM =================
// C(MxN) fp32 = A(MxK) @ B^T with A hi/lo (M,K), B hi/lo (N,K) K-major.
// 128x128 CTA tile, BK=32, double-buffered cp.async, 8 warps (2m x 4n), warp 64x32.
static const int TILE_B = 128 * 40 * 2;          // 10240 B per operand tile (80B row stride)
static const int BUF_B  = 4 * TILE_B;            // 40960 B
static const int GEMM_SMEM = 2 * BUF_B;          // 81920 B

__device__ __forceinline__ void load_chunk(
    const __nv_bfloat16* __restrict__ Ahi, const __nv_bfloat16* __restrict__ Alo,
    const __nv_bfloat16* __restrict__ Bhi, const __nv_bfloat16* __restrict__ Blo,
    int m0, int n0, int k0, int K, uint32_t smbuf, int tid)
{
#pragma unroll
    for (int t = 0; t < 4; t++) {
        const __nv_bfloat16* src =
            (t == 0) ? Ahi + (size_t)m0 * K + k0 :
            (t == 1) ? Alo + (size_t)m0 * K + k0 :
            (t == 2) ? Bhi + (size_t)n0 * K + k0 :
                       Blo + (size_t)n0 * K + k0;
        uint32_t dstb = smbuf + t * TILE_B;
#pragma unroll
        for (int v = 0; v < 2; v++) {
            int idx = v * 256 + tid;             // 512 16B vectors per tile
            int row = idx >> 2, col16 = idx & 3;
            cp_async16(dstb + row * 80 + col16 * 16,
                       src + (size_t)row * K + col16 * 8);
        }
    }
}

__device__ __forceinline__ void gemm_body(
    const __nv_bfloat16* __restrict__ Ahi, const __nv_bfloat16* __restrict__ Alo,
    const __nv_bfloat16* __restrict__ Bhi, const __nv_bfloat16* __restrict__ Blo,
    float* __restrict__ C, int m0, int n0, int N, int K, uint32_t smb)
{
    const int tid = threadIdx.x;
    const int lane = tid & 31, wid = tid >> 5;
    const int warp_m = wid >> 2;
    const int warp_n = wid & 3;

    float acc[4][4][4];
#pragma unroll
    for (int i = 0; i < 4; i++)
#pragma unroll
        for (int j = 0; j < 4; j++)
#pragma unroll
            for (int r = 0; r < 4; r++) acc[i][j][r] = 0.f;

    const int nc = K >> 5;
    load_chunk(Ahi, Alo, Bhi, Blo, m0, n0, 0, K, smb, tid);
    CP_COMMIT();

    const int a_row = warp_m * 64 + (lane & 15);
    const int a_colb = ((lane >> 4) << 3) * 2;
    const int b_row = warp_n * 32 + (lane & 7);
    const int b_colb = (((lane >> 3) & 1) << 3) * 2;

    for (int c = 0; c < nc; c++) {
        uint32_t buf = smb + (c & 1) * BUF_B;
        if (c + 1 < nc) {
            load_chunk(Ahi, Alo, Bhi, Blo, m0, n0, (c + 1) << 5, K,
                       smb + ((c + 1) & 1) * BUF_B, tid);
            CP_COMMIT();
            CP_WAIT(1);
        } else {
            CP_WAIT(0);
        }
        __syncthreads();

#pragma unroll
        for (int ks = 0; ks < 2; ks++) {
            const int ksb = ks * 32;
            uint32_t ah[4][4], al[4][4], bh[4][2], bl[4][2];
#pragma unroll
            for (int mt = 0; mt < 4; mt++) {
                uint32_t rowoff = (uint32_t)(a_row + mt * 16) * 80 + ksb + a_colb;
                ldm_x4(ah[mt], buf + 0 * TILE_B + rowoff);
                ldm_x4(al[mt], buf + 1 * TILE_B + rowoff);
            }
#pragma unroll
            for (int nt = 0; nt < 4; nt++) {
                uint32_t rowoff = (uint32_t)(b_row + nt * 8) * 80 + ksb + b_colb;
                ldm_x2(bh[nt], buf + 2 * TILE_B + rowoff);
                ldm_x2(bl[nt], buf + 3 * TILE_B + rowoff);
            }
#pragma unroll
            for (int mt = 0; mt < 4; mt++)
#pragma unroll
                for (int nt = 0; nt < 4; nt++) {
                    mma_bf16(acc[mt][nt], ah[mt], bh[nt]);
                    mma_bf16(acc[mt][nt], ah[mt], bl[nt]);
                    mma_bf16(acc[mt][nt], al[mt], bh[nt]);
                }
        }
        __syncthreads();
    }

    const int cm = lane >> 2, cn = (lane & 3) << 1;
#pragma unroll
    for (int mt = 0; mt < 4; mt++) {
        int gm = m0 + warp_m * 64 + mt * 16 + cm;
#pragma unroll
        for (int nt = 0; nt < 4; nt++) {
            int gn = n0 + warp_n * 32 + nt * 8 + cn;
            float* cp0 = C + (size_t)gm * N + gn;
            cp0[0] = acc[mt][nt][0];
            cp0[1] = acc[mt][nt][1];
            float* cp1 = C + (size_t)(gm + 8) * N + gn;
            cp1[0] = acc[mt][nt][2];
            cp1[1] = acc[mt][nt][3];
        }
    }
}

__global__ __launch_bounds__(256, 1) void gemm_mma_kernel(
    const __nv_bfloat16* __restrict__ Ahi, const __nv_bfloat16* __restrict__ Alo,
    const __nv_bfloat16* __restrict__ Bhi, const __nv_bfloat16* __restrict__ Blo,
    float* __restrict__ C, int M, int N, int K)
{
    extern __shared__ char sm[];
    gemm_body(Ahi, Alo, Bhi, Blo, C, blockIdx.y * 128, blockIdx.x * 128, N, K,
              smem_u32(sm));
}

// fused QKV projection: grid.x = 24 (16 Q col-tiles, 4 K, 4 V), grid.y = 32
__global__ __launch_bounds__(256, 1) void gemm_qkv_kernel(
    const __nv_bfloat16* __restrict__ xhi, const __nv_bfloat16* __restrict__ xlo,
    const __nv_bfloat16* __restrict__ wqh, const __nv_bfloat16* __restrict__ wql,
    const __nv_bfloat16* __restrict__ wkh, const __nv_bfloat16* __restrict__ wkl,
    const __nv_bfloat16* __restrict__ wvh, const __nv_bfloat16* __restrict__ wvl,
    float* __restrict__ qp, float* __restrict__ kp, float* __restrict__ vp)
{
    extern __shared__ char sm[];
    int bx = blockIdx.x;
    const __nv_bfloat16 *bh_, *bl_;
    float* C;
    int N, n0;
    if (bx < 16)      { bh_ = wqh; bl_ = wql; C = qp; N = 2048; n0 = bx * 128; }
    else if (bx < 20) { bh_ = wkh; bl_ = wkl; C = kp; N = 512;  n0 = (bx - 16) * 128; }
    else              { bh_ = wvh; bl_ = wvl; C = vp; N = 512;  n0 = (bx - 20) * 128; }
    gemm_body(xhi, xlo, bh_, bl_, C, blockIdx.y * 128, n0, N, 2048, smem_u32(sm));
}

// ---------------- RoPE on Q: (B,S,H,D) proj -> (B,H,S,D) bf16 hi/lo ----------------
__global__ __launch_bounds__(256) void rope_q_kernel(
    const float* __restrict__ qp, const float* __restrict__ cosx,
    const float* __restrict__ sinx, __nv_bfloat16* __restrict__ qh,
    __nv_bfloat16* __restrict__ ql)
{
    int i = blockIdx.x * blockDim.x + threadIdx.x;   // ordered (b,h,s,d)
    int d = i & 63;
    int s = (i >> 6) & 2047;
    int h = (i >> 17) & 31;
    int b = i >> 22;
    size_t src = ((size_t)(b * 2048 + s)) * 2048 + h * 64;
    float v1 = qp[src + d];
    int d2 = (d < 32) ? d + 32 : d - 32;
    float v2 = qp[src + d2];
    float c = cosx[s * 64 + d], sn = sinx[s * 64 + d];
    float val = v1 * c + ((d < 32) ? -v2 : v2) * sn;
    __nv_bfloat16 hh = __float2bfloat16(val);
    qh[i] = hh;
    ql[i] = __float2bfloat16(val - __bfloat162float(hh));
}

// ---- RoPE K + copy V: fp32 into d_out (required) + bf16 hi/lo for attention ----
__global__ __launch_bounds__(256) void rope_kv_kernel(
    const float* __restrict__ kp, const float* __restrict__ vp,
    const float* __restrict__ cosx, const float* __restrict__ sinx,
    float* __restrict__ ko, float* __restrict__ vo,
    __nv_bfloat16* __restrict__ kh, __nv_bfloat16* __restrict__ kl,
    __nv_bfloat16* __restrict__ vh, __nv_bfloat16* __restrict__ vl)
{
    int i = blockIdx.x * blockDim.x + threadIdx.x;   // ordered (b,kv,s,d)
    int d = i & 63;
    int s = (i >> 6) & 2047;
    int kv = (i >> 17) & 7;
    int b = i >> 20;
    size_t src = ((size_t)(b * 2048 + s)) * 512 + kv * 64;
    float v1 = kp[src + d];
    int d2 = (d < 32) ? d + 32 : d - 32;
    float v2 = kp[src + d2];
    float c = cosx[s * 64 + d], sn = sinx[s * 64 + d];
    float kval = v1 * c + ((d < 32) ? -v2 : v2) * sn;
    float vval = vp[src + d];
    ko[i] = kval;
    vo[i] = vval;
    __nv_bfloat16 khh = __float2bfloat16(kval);
    kh[i] = khh;
    kl[i] = __float2bfloat16(kval - __bfloat162float(khh));
    __nv_bfloat16 vhh = __float2bfloat16(vval);
    vh[i] = vhh;
    vl[i] = __float2bfloat16(vval - __bfloat162float(vhh));
}

// ---------------- Flash attention: mma.sync bf16 split-precision ----------------
// Q tile 128 rows, KV tiles 64. 8 warps; warp owns 16 Q rows.
// Smem rows padded to 144 B (64 bf16 -> +8 pad) for conflict-free ldmatrix.
// Layout (bytes): Qh[0,18432) Ql[18432,36864) then 2 KV buffers of
//   {Kh,Kl,Vh,Vl} x 64*144 = 9216 each (36864 per buffer).
static const int FL_QH = 0;
static const int FL_QL = 18432;
static const int FL_KV0 = 36864;
static const int FL_KVBUF = 36864;
static const int FL_SMEM = 36864 + 2 * 36864;     // 110592

__device__ __forceinline__ void fl_load_kv(
    const __nv_bfloat16* kh, const __nv_bfloat16* kl,
    const __nv_bfloat16* vh, const __nv_bfloat16* vl,
    int kn, uint32_t bufb, int tid)
{
    const __nv_bfloat16* srcs[4] = { kh + kn * 64 * 64, kl + kn * 64 * 64,
                                     vh + kn * 64 * 64, vl + kn * 64 * 64 };
#pragma unroll
    for (int t = 0; t < 4; t++) {
        uint32_t dstb = bufb + t * 9216;
#pragma unroll
        for (int v = 0; v < 2; v++) {
            int idx = v * 256 + tid;             // 512 vectors per tile
            int row = idx >> 3, c16 = idx & 7;
            cp_async16(dstb + row * 144 + c16 * 16, srcs[t] + row * 64 + c16 * 8);
        }
    }
}

__global__ __launch_bounds__(256, 1) void flash_mma_kernel(
    const __nv_bfloat16* __restrict__ Qh, const __nv_bfloat16* __restrict__ Ql,
    const __nv_bfloat16* __restrict__ Kh, const __nv_bfloat16* __restrict__ Kl,
    const __nv_bfloat16* __restrict__ Vh, const __nv_bfloat16* __restrict__ Vl,
    __nv_bfloat16* __restrict__ Oh, __nv_bfloat16* __restrict__ Ol)
{
    extern __shared__ char sm[];
    uint32_t smb = smem_u32(sm);
    const int tid = threadIdx.x, lane = tid & 31, w = tid >> 5;
    const int mT = blockIdx.x;            // 0..15 (128 rows each)
    const int bh = blockIdx.y;            // b*32+h
    const int b = bh >> 5, h = bh & 31, kvh = h >> 2;

    const __nv_bfloat16* qh = Qh + ((size_t)bh * 2048 + mT * 128) * 64;
    const __nv_bfloat16* qlp = Ql + ((size_t)bh * 2048 + mT * 128) * 64;
    const size_t kvoff = (size_t)(b * 8 + kvh) * 2048 * 64;
    const __nv_bfloat16* khp = Kh + kvoff;
    const __nv_bfloat16* klp = Kl + kvoff;
    const __nv_bfloat16* vhp = Vh + kvoff;
    const __nv_bfloat16* vlp = Vl + kvoff;

    // load Q hi/lo (1024 16B vectors per tile)
#pragma unroll
    for (int v = 0; v < 4; v++) {
        int idx = v * 256 + tid;
        int row = idx >> 3, c16 = idx & 7;
        cp_async16(smb + FL_QH + row * 144 + c16 * 16, qh + row * 64 + c16 * 8);
        cp_async16(smb + FL_QL + row * 144 + c16 * 16, qlp + row * 64 + c16 * 8);
    }
    CP_COMMIT();

    const int ntiles = 2 * mT + 2;
    fl_load_kv(khp, klp, vhp, vlp, 0, smb + FL_KV0, tid);
    CP_COMMIT();

    float m0 = -1e30f, m1 = -1e30f, l0 = 0.f, l1 = 0.f;
    float o[8][4];
#pragma unroll
    for (int nt = 0; nt < 8; nt++)
#pragma unroll
        for (int j = 0; j < 4; j++) o[nt][j] = 0.f;

    const int wr0 = mT * 128 + w * 16;    // warp's first global row
    const uint32_t q_addr_base =
        smb + (uint32_t)(w * 16 + (lane & 15)) * 144 + ((lane >> 4) << 4);
    const uint32_t k_row = (lane & 7);
    const uint32_t k_cb = ((lane >> 3) & 1) << 4;

    for (int kn = 0; kn < ntiles; kn++) {
        uint32_t kbuf = smb + FL_KV0 + (kn & 1) * FL_KVBUF;
        if (kn + 1 < ntiles) {
            fl_load_kv(khp, klp, vhp, vlp, kn + 1,
                       smb + FL_KV0 + ((kn + 1) & 1) * FL_KVBUF, tid);
            CP_COMMIT();
            CP_WAIT(1);
        } else {
            CP_WAIT(0);
        }
        __syncthreads();

        if (64 * kn <= wr0 + 15) {        // otherwise fully above diagonal: skip
            // ---- S = Q @ K^T (3 split products) ----
            float s[8][4];
#pragma unroll
            for (int nt = 0; nt < 8; nt++)
#pragma unroll
                for (int j = 0; j < 4; j++) s[nt][j] = 0.f;

#pragma unroll
            for (int ks = 0; ks < 4; ks++) {
                uint32_t aqh[4], aql[4];
                uint32_t qa = q_addr_base + ks * 32;
                ldm_x4(aqh, qa + FL_QH);
                ldm_x4(aql, qa + FL_QL);
#pragma unroll
                for (int nt = 0; nt < 8; nt++) {
                    uint32_t bkh[2], bkl[2];
                    uint32_t ka = kbuf + (nt * 8 + k_row) * 144 + ks * 32 + k_cb;
                    ldm_x2(bkh, ka);
                    ldm_x2(bkl, ka + 9216);
                    mma_bf16(s[nt], aqh, bkh);
                    mma_bf16(s[nt], aqh, bkl);
                    mma_bf16(s[nt], aql, bkh);
                }
            }

            // ---- scale + causal mask ----
            const bool needm = (64 * kn + 63 > wr0);
            const int rg0 = wr0 + (lane >> 2);
            const int rg1 = rg0 + 8;
            const int cbase = 64 * kn + 2 * (lane & 3);
#pragma unroll
            for (int nt = 0; nt < 8; nt++) {
                int c0 = cbase + 8 * nt;
#pragma unroll
                for (int j = 0; j < 4; j++) {
                    s[nt][j] *= 0.125f;
                    if (needm) {
                        int col = c0 + (j & 1);
                        int row = (j < 2) ? rg0 : rg1;
                        if (col > row) s[nt][j] = -1e30f;
                    }
                }
            }

            // ---- online softmax (rows rg0, rg1 per thread) ----
            float mx0 = -1e30f, mx1 = -1e30f;
#pragma unroll
            for (int nt = 0; nt < 8; nt++) {
                mx0 = fmaxf(mx0, fmaxf(s[nt][0], s[nt][1]));
                mx1 = fmaxf(mx1, fmaxf(s[nt][2], s[nt][3]));
            }
#pragma unroll
            for (int off = 1; off <= 2; off <<= 1) {
                mx0 = fmaxf(mx0, __shfl_xor_sync(0xffffffffu, mx0, off));
                mx1 = fmaxf(mx1, __shfl_xor_sync(0xffffffffu, mx1, off));
            }
            float mn0 = fmaxf(m0, mx0), mn1 = fmaxf(m1, mx1);
            float fac0 = __expf(m0 - mn0), fac1 = __expf(m1 - mn1);
            float ps0 = 0.f, ps1 = 0.f;
#pragma unroll
            for (int nt = 0; nt < 8; nt++) {
                s[nt][0] = __expf(s[nt][0] - mn0);
                s[nt][1] = __expf(s[nt][1] - mn0);
                s[nt][2] = __expf(s[nt][2] - mn1);
                s[nt][3] = __expf(s[nt][3] - mn1);
                ps0 += s[nt][0] + s[nt][1];
                ps1 += s[nt][2] + s[nt][3];
            }
#pragma unroll
            for (int off = 1; off <= 2; off <<= 1) {
                ps0 += __shfl_xor_sync(0xffffffffu, ps0, off);
                ps1 += __shfl_xor_sync(0xffffffffu, ps1, off);
            }
            l0 = l0 * fac0 + ps0;
            l1 = l1 * fac1 + ps1;
            m0 = mn0; m1 = mn1;
#pragma unroll
            for (int nt = 0; nt < 8; nt++) {
                o[nt][0] *= fac0; o[nt][1] *= fac0;
                o[nt][2] *= fac1; o[nt][3] *= fac1;
            }

            // ---- O += P @ V (3 split products; V B-frag via ldmatrix.trans) ----
#pragma unroll
            for (int ks = 0; ks < 4; ks++) {
                // A-frag from P (scores of ntiles 2ks, 2ks+1), split hi/lo
                uint32_t ph[4], pl[4];
#pragma unroll
                for (int half = 0; half < 2; half++) {
                    const float* sv = s[2 * ks + half];
#pragma unroll
                    for (int rr = 0; rr < 2; rr++) {
                        float v0 = sv[2 * rr], v1 = sv[2 * rr + 1];
                        float h0 = __bfloat162float(__float2bfloat16(v0));
                        float h1 = __bfloat162float(__float2bfloat16(v1));
                        ph[half * 2 + rr] = pack_bf16(v0, v1);
                        pl[half * 2 + rr] = pack_bf16(v0 - h0, v1 - h1);
                    }
                }
#pragma unroll
                for (int nt = 0; nt < 8; nt++) {
                    uint32_t bvh[2], bvl[2];
                    uint32_t va = kbuf + 18432 +
                                  (uint32_t)(16 * ks + (lane & 15)) * 144 + nt * 16;
                    ldm_x2t(bvh, va);
                    ldm_x2t(bvl, va + 9216);
                    mma_bf16(o[nt], ph, bvh);
                    mma_bf16(o[nt], ph, bvl);
                    mma_bf16(o[nt], pl, bvh);
                }
            }
        }
        __syncthreads();
    }

    // ---- epilogue: write attn hi/lo in (B,S,H,D) ----
    float inv0 = 1.f / l0, inv1 = 1.f / l1;
    int gr0 = wr0 + (lane >> 2);
    size_t base0 = ((size_t)(b * 2048 + gr0)) * 2048 + h * 64;
    size_t base1 = base0 + (size_t)8 * 2048;
#pragma unroll
    for (int nt = 0; nt < 8; nt++) {
        int d0 = nt * 8 + 2 * (lane & 3);
        float v0 = o[nt][0] * inv0, v1 = o[nt][1] * inv0;
        float h0 = __bfloat162float(__float2bfloat16(v0));
        float h1 = __bfloat162float(__float2bfloat16(v1));
        *(uint32_t*)(Oh + base0 + d0) = pack_bf16(v0, v1);
        *(uint32_t*)(Ol + base0 + d0) = pack_bf16(v0 - h0, v1 - h1);
        float v2 = o[nt][2] * inv1, v3 = o[nt][3] * inv1;
        float h2 = __bfloat162float(__float2bfloat16(v2));
        float h3 = __bfloat162float(__float2bfloat16(v3));
        *(uint32_t*)(Oh + base1 + d0) = pack_bf16(v2, v3);
        *(uint32_t*)(Ol + base1 + d0) = pack_bf16(v2 - h2, v3 - h3);
    }
}

extern "C" void kernel_launch(void* const* d_in, const int* in_sizes, int n_in,
                              void* d_out, int out_size)
{
    const float* x    = (const float*)d_in[0];
    // d_in[1] = mask (deterministic causal triu) — computed analytically
    const float* cosx = (const float*)d_in[2];
    const float* sinx = (const float*)d_in[3];
    const float* Wq   = (const float*)d_in[4];
    const float* Wk   = (const float*)d_in[5];
    const float* Wv   = (const float*)d_in[6];
    const float* Wo   = (const float*)d_in[7];

    float* out  = (float*)d_out;          // (B,S,E)
    float* outK = out + 8388608;          // (B,KV,S,D)
    float* outV = outK + 2097152;

    float *qproj, *kproj, *vproj;
    cudaGetSymbolAddress((void**)&qproj, g_qproj);
    cudaGetSymbolAddress((void**)&kproj, g_kproj);
    cudaGetSymbolAddress((void**)&vproj, g_vproj);

    __nv_bfloat16 *qrh, *qrl, *khi, *klo, *vhi, *vlo;
    cudaGetSymbolAddress((void**)&qrh, g_qrh);
    cudaGetSymbolAddress((void**)&qrl, g_qrl);
    cudaGetSymbolAddress((void**)&khi, g_khi);
    cudaGetSymbolAddress((void**)&klo, g_klo);
    cudaGetSymbolAddress((void**)&vhi, g_vhi);
    cudaGetSymbolAddress((void**)&vlo, g_vlo);

    __nv_bfloat16 *xhi, *xlo, *ahi, *alo;
    __nv_bfloat16 *wqh, *wql, *wkh, *wkl, *wvh, *wvl, *woh, *wol;
    cudaGetSymbolAddress((void**)&xhi, g_xhi);
    cudaGetSymbolAddress((void**)&xlo, g_xlo);
    cudaGetSymbolAddress((void**)&ahi, g_ahi);
    cudaGetSymbolAddress((void**)&alo, g_alo);
    cudaGetSymbolAddress((void**)&wqh, g_wqt_hi);
    cudaGetSymbolAddress((void**)&wql, g_wqt_lo);
    cudaGetSymbolAddress((void**)&wkh, g_wkt_hi);
    cudaGetSymbolAddress((void**)&wkl, g_wkt_lo);
    cudaGetSymbolAddress((void**)&wvh, g_wvt_hi);
    cudaGetSymbolAddress((void**)&wvl, g_wvt_lo);
    cudaGetSymbolAddress((void**)&woh, g_wot_hi);
    cudaGetSymbolAddress((void**)&wol, g_wot_lo);

    cudaFuncSetAttribute(gemm_mma_kernel,
                         cudaFuncAttributeMaxDynamicSharedMemorySize, GEMM_SMEM);
    cudaFuncSetAttribute(gemm_qkv_kernel,
                         cudaFuncAttributeMaxDynamicSharedMemorySize, GEMM_SMEM);
    cudaFuncSetAttribute(flash_mma_kernel,
                         cudaFuncAttributeMaxDynamicSharedMemorySize, FL_SMEM);

    dim3 blk(256);
    dim3 tblk(32, 8);

    // Preprocess: split x; transpose+split weights
    split_kernel<<<8388608 / 256, blk>>>(x, xhi, xlo);
    transpose_split_kernel<<<dim3(64, 64), tblk>>>(Wq, wqh, wql, 2048, 2048);
    transpose_split_kernel<<<dim3(16, 64), tblk>>>(Wk, wkh, wkl, 2048, 512);
    transpose_split_kernel<<<dim3(16, 64), tblk>>>(Wv, wvh, wvl, 2048, 512);
    transpose_split_kernel<<<dim3(64, 64), tblk>>>(Wo, woh, wol, 2048, 2048);

    // Fused QKV projections (tensor cores, split-precision)
    gemm_qkv_kernel<<<dim3(24, 32), blk, GEMM_SMEM>>>(
        xhi, xlo, wqh, wql, wkh, wkl, wvh, wvl, qproj, kproj, vproj);

    // RoPE + layout transforms (fp32 K/V straight into d_out, bf16 hi/lo for attn)
    rope_q_kernel<<<8388608 / 256, 256>>>(qproj, cosx, sinx, qrh, qrl);
    rope_kv_kernel<<<2097152 / 256, 256>>>(kproj, vproj, cosx, sinx,
                                           outK, outV, khi, klo, vhi, vlo);

    // Flash attention on tensor cores (split-precision), emits hi/lo directly
    flash_mma_kernel<<<dim3(16, 64), blk, FL_SMEM>>>(
        qrh, qrl, khi, klo, vhi, vlo, ahi, alo);

    // Output projection
    gemm_mma_kernel<<<dim3(16, 32), blk, GEMM_SMEM>>>(
        ahi, alo, woh, wol, out, 4096, 2048, 2048);
}

// round 7
// speedup vs baseline: 3.0316x; 1.0003x over previous
#include <cuda_runtime.h>
#include <cuda_bf16.h>
#include <math.h>
#include <stdint.h>

// Problem constants: B=2, S=2048, E=2048, NH=32, NKV=8, HD=64, GROUP=4, M=B*S=4096

// -------- scratch (static device globals; allocation-free) --------
__device__ float g_qproj[4096 * 2048];
__device__ float g_kproj[4096 * 512];
__device__ float g_vproj[4096 * 512];

__device__ __nv_bfloat16 g_qrh[4096 * 2048];   // roped Q hi (B,H,S,D)
__device__ __nv_bfloat16 g_qrl[4096 * 2048];   // roped Q lo
__device__ __nv_bfloat16 g_khi[2097152];       // roped K hi (B,KV,S,D)
__device__ __nv_bfloat16 g_klo[2097152];
__device__ __nv_bfloat16 g_vhi[2097152];
__device__ __nv_bfloat16 g_vlo[2097152];

__device__ __nv_bfloat16 g_xhi[4096 * 2048];
__device__ __nv_bfloat16 g_xlo[4096 * 2048];
__device__ __nv_bfloat16 g_ahi[4096 * 2048];   // attn out hi (B,S,H,D)
__device__ __nv_bfloat16 g_alo[4096 * 2048];
__device__ __nv_bfloat16 g_wqt_hi[2048 * 2048];
__device__ __nv_bfloat16 g_wqt_lo[2048 * 2048];
__device__ __nv_bfloat16 g_wkt_hi[512 * 2048];
__device__ __nv_bfloat16 g_wkt_lo[512 * 2048];
__device__ __nv_bfloat16 g_wvt_hi[512 * 2048];
__device__ __nv_bfloat16 g_wvt_lo[512 * 2048];
__device__ __nv_bfloat16 g_wot_hi[2048 * 2048];
__device__ __nv_bfloat16 g_wot_lo[2048 * 2048];

// ================= PTX helpers (compute_103-safe) =================
__device__ __forceinline__ uint32_t smem_u32(const void* p) {
    uint32_t a;
    asm("{ .reg .u64 t; cvta.to.shared.u64 t, %1; cvt.u32.u64 %0, t; }" : "=r"(a) : "l"(p));
    return a;
}
__device__ __forceinline__ void cp_async16(uint32_t dst, const void* src) {
    asm volatile("cp.async.cg.shared.global [%0], [%1], 16;" :: "r"(dst), "l"(src));
}
#define CP_COMMIT() asm volatile("cp.async.commit_group;" ::: "memory")
#define CP_WAIT(n)  asm volatile("cp.async.wait_group %0;" :: "n"(n) : "memory")

__device__ __forceinline__ void ldm_x4(uint32_t* r, uint32_t addr) {
    asm volatile("ldmatrix.sync.aligned.m8n8.x4.shared.b16 {%0,%1,%2,%3}, [%4];"
                 : "=r"(r[0]), "=r"(r[1]), "=r"(r[2]), "=r"(r[3]) : "r"(addr));
}
__device__ __forceinline__ void ldm_x2(uint32_t* r, uint32_t addr) {
    asm volatile("ldmatrix.sync.aligned.m8n8.x2.shared.b16 {%0,%1}, [%2];"
                 : "=r"(r[0]), "=r"(r[1]) : "r"(addr));
}
__device__ __forceinline__ void ldm_x2t(uint32_t* r, uint32_t addr) {
    asm volatile("ldmatrix.sync.aligned.m8n8.x2.trans.shared.b16 {%0,%1}, [%2];"
                 : "=r"(r[0]), "=r"(r[1]) : "r"(addr));
}
__device__ __forceinline__ void mma_bf16(float* c, const uint32_t* a, const uint32_t* b) {
    asm volatile(
        "mma.sync.aligned.m16n8k16.row.col.f32.bf16.bf16.f32 "
        "{%0,%1,%2,%3}, {%4,%5,%6,%7}, {%8,%9}, {%0,%1,%2,%3};"
        : "+f"(c[0]), "+f"(c[1]), "+f"(c[2]), "+f"(c[3])
        : "r"(a[0]), "r"(a[1]), "r"(a[2]), "r"(a[3]), "r"(b[0]), "r"(b[1]));
}
// pack two fp32 into bf16x2: first arg -> low half, second -> high half
__device__ __forceinline__ uint32_t pack_bf16(float lo, float hi) {
    uint32_t r;
    asm("cvt.rn.bf16x2.f32 %0, %1, %2;" : "=r"(r) : "f"(hi), "f"(lo));
    return r;
}

// ================= elementwise split fp32 -> bf16 hi/lo =================
__global__ __launch_bounds__(256) void split_kernel(
    const float* __restrict__ src, __nv_bfloat16* __restrict__ hi,
    __nv_bfloat16* __restrict__ lo)
{
    int i = blockIdx.x * 256 + threadIdx.x;
    float v = src[i];
    __nv_bfloat16 h = __float2bfloat16(v);
    hi[i] = h;
    lo[i] = __float2bfloat16(v - __bfloat162float(h));
}

// ============ weight transpose + split: W(K x N) -> WT_hi/lo (N x K) ============
__global__ __launch_bounds__(256) void transpose_split_kernel(
    const float* __restrict__ W, __nv_bfloat16* __restrict__ hi,
    __nv_bfloat16* __restrict__ lo, int K, int N)
{
    __shared__ float t[32][33];
    int n0 = blockIdx.x * 32, k0 = blockIdx.y * 32;
    int tx = threadIdx.x, ty = threadIdx.y;   // 32 x 8
#pragma unroll
    for (int i = 0; i < 32; i += 8)
        t[ty + i][tx] = W[(size_t)(k0 + ty + i) * N + n0 + tx];
    __syncthreads();
#pragma unroll
    for (int i = 0; i < 32; i += 8) {
        float v = t[tx][ty + i];
        __nv_bfloat16 h = __float2bfloat16(v);
        size_t o = (size_t)(n0 + ty + i) * K + k0 + tx;
        hi[o] = h;
        lo[o] = __float2bfloat16(v - __bfloat162float(h));
    }
}

// ================= mma.sync split-bf16 GEMM =================
// C(MxN) fp32 = A(MxK) @ B^T with A hi/lo (M,K), B hi/lo (N,K) K-major.
// 128x128 CTA tile, BK=32, double-buffered cp.async, 8 warps (2m x 4n), warp 64x32.
static const int TILE_B = 128 * 40 * 2;          // 10240 B per operand tile (80B row stride)
static const int BUF_B  = 4 * TILE_B;            // 40960 B
static const int GEMM_SMEM = 2 * BUF_B;          // 81920 B

__device__ __forceinline__ void load_chunk(
    const __nv_bfloat16* __restrict__ Ahi, const __nv_bfloat16* __restrict__ Alo,
    const __nv_bfloat16* __restrict__ Bhi, const __nv_bfloat16* __restrict__ Blo,
    int m0, int n0, int k0, int K, uint32_t smbuf, int tid)
{
#pragma unroll
    for (int t = 0; t < 4; t++) {
        const __nv_bfloat16* src =
            (t == 0) ? Ahi + (size_t)m0 * K + k0 :
            (t == 1) ? Alo + (size_t)m0 * K + k0 :
            (t == 2) ? Bhi + (size_t)n0 * K + k0 :
                       Blo + (size_t)n0 * K + k0;
        uint32_t dstb = smbuf + t * TILE_B;
#pragma unroll
        for (int v = 0; v < 2; v++) {
            int idx = v * 256 + tid;             // 512 16B vectors per tile
            int row = idx >> 2, col16 = idx & 3;
            cp_async16(dstb + row * 80 + col16 * 16,
                       src + (size_t)row * K + col16 * 8);
        }
    }
}

__device__ __forceinline__ void gemm_body(
    const __nv_bfloat16* __restrict__ Ahi, const __nv_bfloat16* __restrict__ Alo,
    const __nv_bfloat16* __restrict__ Bhi, const __nv_bfloat16* __restrict__ Blo,
    float* __restrict__ C, int m0, int n0, int N, int K, uint32_t smb)
{
    const int tid = threadIdx.x;
    const int lane = tid & 31, wid = tid >> 5;
    const int warp_m = wid >> 2;
    const int warp_n = wid & 3;

    float acc[4][4][4];
#pragma unroll
    for (int i = 0; i < 4; i++)
#pragma unroll
        for (int j = 0; j < 4; j++)
#pragma unroll
            for (int r = 0; r < 4; r++) acc[i][j][r] = 0.f;

    const int nc = K >> 5;
    load_chunk(Ahi, Alo, Bhi, Blo, m0, n0, 0, K, smb, tid);
    CP_COMMIT();

    const int a_row = warp_m * 64 + (lane & 15);
    const int a_colb = ((lane >> 4) << 3) * 2;
    const int b_row = warp_n * 32 + (lane & 7);
    const int b_colb = (((lane >> 3) & 1) << 3) * 2;

    for (int c = 0; c < nc; c++) {
        uint32_t buf = smb + (c & 1) * BUF_B;
        if (c + 1 < nc) {
            load_chunk(Ahi, Alo, Bhi, Blo, m0, n0, (c + 1) << 5, K,
                       smb + ((c + 1) & 1) * BUF_B, tid);
            CP_COMMIT();
            CP_WAIT(1);
        } else {
            CP_WAIT(0);
        }
        __syncthreads();

#pragma unroll
        for (int ks = 0; ks < 2; ks++) {
            const int ksb = ks * 32;
            uint32_t ah[4][4], al[4][4], bh[4][2], bl[4][2];
#pragma unroll
            for (int mt = 0; mt < 4; mt++) {
                uint32_t rowoff = (uint32_t)(a_row + mt * 16) * 80 + ksb + a_colb;
                ldm_x4(ah[mt], buf + 0 * TILE_B + rowoff);
                ldm_x4(al[mt], buf + 1 * TILE_B + rowoff);
            }
#pragma unroll
            for (int nt = 0; nt < 4; nt++) {
                uint32_t rowoff = (uint32_t)(b_row + nt * 8) * 80 + ksb + b_colb;
                ldm_x2(bh[nt], buf + 2 * TILE_B + rowoff);
                ldm_x2(bl[nt], buf + 3 * TILE_B + rowoff);
            }
#pragma unroll
            for (int mt = 0; mt < 4; mt++)
#pragma unroll
                for (int nt = 0; nt < 4; nt++) {
                    mma_bf16(acc[mt][nt], ah[mt], bh[nt]);
                    mma_bf16(acc[mt][nt], ah[mt], bl[nt]);
                    mma_bf16(acc[mt][nt], al[mt], bh[nt]);
                }
        }
        __syncthreads();
    }

    const int cm = lane >> 2, cn = (lane & 3) << 1;
#pragma unroll
    for (int mt = 0; mt < 4; mt++) {
        int gm = m0 + warp_m * 64 + mt * 16 + cm;
#pragma unroll
        for (int nt = 0; nt < 4; nt++) {
            int gn = n0 + warp_n * 32 + nt * 8 + cn;
            float* cp0 = C + (size_t)gm * N + gn;
            cp0[0] = acc[mt][nt][0];
            cp0[1] = acc[mt][nt][1];
            float* cp1 = C + (size_t)(gm + 8) * N + gn;
            cp1[0] = acc[mt][nt][2];
            cp1[1] = acc[mt][nt][3];
        }
    }
}

__global__ __launch_bounds__(256, 1) void gemm_mma_kernel(
    const __nv_bfloat16* __restrict__ Ahi, const __nv_bfloat16* __restrict__ Alo,
    const __nv_bfloat16* __restrict__ Bhi, const __nv_bfloat16* __restrict__ Blo,
    float* __restrict__ C, int M, int N, int K)
{
    extern __shared__ char sm[];
    gemm_body(Ahi, Alo, Bhi, Blo, C, blockIdx.y * 128, blockIdx.x * 128, N, K,
              smem_u32(sm));
}

// fused QKV projection: grid.x = 24 (16 Q col-tiles, 4 K, 4 V), grid.y = 32
__global__ __launch_bounds__(256, 1) void gemm_qkv_kernel(
    const __nv_bfloat16* __restrict__ xhi, const __nv_bfloat16* __restrict__ xlo,
    const __nv_bfloat16* __restrict__ wqh, const __nv_bfloat16* __restrict__ wql,
    const __nv_bfloat16* __restrict__ wkh, const __nv_bfloat16* __restrict__ wkl,
    const __nv_bfloat16* __restrict__ wvh, const __nv_bfloat16* __restrict__ wvl,
    float* __restrict__ qp, float* __restrict__ kp, float* __restrict__ vp)
{
    extern __shared__ char sm[];
    int bx = blockIdx.x;
    const __nv_bfloat16 *bh_, *bl_;
    float* C;
    int N, n0;
    if (bx < 16)      { bh_ = wqh; bl_ = wql; C = qp; N = 2048; n0 = bx * 128; }
    else if (bx < 20) { bh_ = wkh; bl_ = wkl; C = kp; N = 512;  n0 = (bx - 16) * 128; }
    else              { bh_ = wvh; bl_ = wvl; C = vp; N = 512;  n0 = (bx - 20) * 128; }
    gemm_body(xhi, xlo, bh_, bl_, C, blockIdx.y * 128, n0, N, 2048, smem_u32(sm));
}

// ---------------- RoPE on Q: (B,S,H,D) proj -> (B,H,S,D) bf16 hi/lo ----------------
__global__ __launch_bounds__(256) void rope_q_kernel(
    const float* __restrict__ qp, const float* __restrict__ cosx,
    const float* __restrict__ sinx, __nv_bfloat16* __restrict__ qh,
    __nv_bfloat16* __restrict__ ql)
{
    int i = blockIdx.x * blockDim.x + threadIdx.x;   // ordered (b,h,s,d)
    int d = i & 63;
    int s = (i >> 6) & 2047;
    int h = (i >> 17) & 31;
    int b = i >> 22;
    size_t src = ((size_t)(b * 2048 + s)) * 2048 + h * 64;
    float v1 = qp[src + d];
    int d2 = (d < 32) ? d + 32 : d - 32;
    float v2 = qp[src + d2];
    float c = cosx[s * 64 + d], sn = sinx[s * 64 + d];
    float val = v1 * c + ((d < 32) ? -v2 : v2) * sn;
    __nv_bfloat16 hh = __float2bfloat16(val);
    qh[i] = hh;
    ql[i] = __float2bfloat16(val - __bfloat162float(hh));
}

// ---- RoPE K + copy V: fp32 into d_out (required) + bf16 hi/lo for attention ----
__global__ __launch_bounds__(256) void rope_kv_kernel(
    const float* __restrict__ kp, const float* __restrict__ vp,
    const float* __restrict__ cosx, const float* __restrict__ sinx,
    float* __restrict__ ko, float* __restrict__ vo,
    __nv_bfloat16* __restrict__ kh, __nv_bfloat16* __restrict__ kl,
    __nv_bfloat16* __restrict__ vh, __nv_bfloat16* __restrict__ vl)
{
    int i = blockIdx.x * blockDim.x + threadIdx.x;   // ordered (b,kv,s,d)
    int d = i & 63;
    int s = (i >> 6) & 2047;
    int kv = (i >> 17) & 7;
    int b = i >> 20;
    size_t src = ((size_t)(b * 2048 + s)) * 512 + kv * 64;
    float v1 = kp[src + d];
    int d2 = (d < 32) ? d + 32 : d - 32;
    float v2 = kp[src + d2];
    float c = cosx[s * 64 + d], sn = sinx[s * 64 + d];
    float kval = v1 * c + ((d < 32) ? -v2 : v2) * sn;
    float vval = vp[src + d];
    ko[i] = kval;
    vo[i] = vval;
    __nv_bfloat16 khh = __float2bfloat16(kval);
    kh[i] = khh;
    kl[i] = __float2bfloat16(kval - __bfloat162float(khh));
    __nv_bfloat16 vhh = __float2bfloat16(vval);
    vh[i] = vhh;
    vl[i] = __float2bfloat16(vval - __bfloat162float(vhh));
}

// ---------------- Flash attention: mma.sync bf16 split-precision ----------------
// Q tile 128 rows, KV tiles 64. 8 warps; warp owns 16 Q rows.
// Q-hi fragments live in registers (loaded once via ldmatrix from a KV buffer
// used as staging); Q-lo stays in smem (register budget for occupancy 2).
// Smem rows padded to 144 B. Layout:
//   [0, 18432)        Q-lo (persistent, 128 rows x 144B)
//   [18432, 55296)    KV buffer A ({Kh,Kl,Vh,Vl} x 9216) -- Q-hi staging at start
//   [55296, 92160)    KV buffer B
static const int FL_QLO  = 0;
static const int FL_BUFA = 18432;
static const int FL_BUFB = 55296;
static const int FL_SMEM = 92160;

__device__ __forceinline__ void fl_load_kv(
    const __nv_bfloat16* kh, const __nv_bfloat16* kl,
    const __nv_bfloat16* vh, const __nv_bfloat16* vl,
    int kn, uint32_t bufb, int tid)
{
    const __nv_bfloat16* srcs[4] = { kh + kn * 64 * 64, kl + kn * 64 * 64,
                                     vh + kn * 64 * 64, vl + kn * 64 * 64 };
#pragma unroll
    for (int t = 0; t < 4; t++) {
        uint32_t dstb = bufb + t * 9216;
#pragma unroll
        for (int v = 0; v < 2; v++) {
            int idx = v * 256 + tid;             // 512 vectors per tile
            int row = idx >> 3, c16 = idx & 7;
            cp_async16(dstb + row * 144 + c16 * 16, srcs[t] + row * 64 + c16 * 8);
        }
    }
}

__global__ __launch_bounds__(256, 2) void flash_mma_kernel(
    const __nv_bfloat16* __restrict__ Qh, const __nv_bfloat16* __restrict__ Ql,
    const __nv_bfloat16* __restrict__ Kh, const __nv_bfloat16* __restrict__ Kl,
    const __nv_bfloat16* __restrict__ Vh, const __nv_bfloat16* __restrict__ Vl,
    __nv_bfloat16* __restrict__ Oh, __nv_bfloat16* __restrict__ Ol)
{
    extern __shared__ char sm[];
    uint32_t smb = smem_u32(sm);
    const int tid = threadIdx.x, lane = tid & 31, w = tid >> 5;
    const int mT = 15 - blockIdx.x;       // longest CTAs first within each row-group
    const int bh = blockIdx.y;            // b*32+h
    const int b = bh >> 5, h = bh & 31, kvh = h >> 2;

    const __nv_bfloat16* qh = Qh + ((size_t)bh * 2048 + mT * 128) * 64;
    const __nv_bfloat16* qlp = Ql + ((size_t)bh * 2048 + mT * 128) * 64;
    const size_t kvoff = (size_t)(b * 8 + kvh) * 2048 * 64;
    const __nv_bfloat16* khp = Kh + kvoff;
    const __nv_bfloat16* klp = Kl + kvoff;
    const __nv_bfloat16* vhp = Vh + kvoff;
    const __nv_bfloat16* vlp = Vl + kvoff;

    // Prologue: Q-hi -> BUFA (staging), Q-lo -> QLO region; then KV0 -> BUFB.
#pragma unroll
    for (int v = 0; v < 4; v++) {
        int idx = v * 256 + tid;
        int row = idx >> 3, c16 = idx & 7;
        cp_async16(smb + FL_BUFA + row * 144 + c16 * 16, qh + row * 64 + c16 * 8);
        cp_async16(smb + FL_QLO + row * 144 + c16 * 16, qlp + row * 64 + c16 * 8);
    }
    CP_COMMIT();
    fl_load_kv(khp, klp, vhp, vlp, 0, smb + FL_BUFB, tid);
    CP_COMMIT();
    CP_WAIT(1);                           // Q group done; KV0 may be in flight
    __syncthreads();

    // Read Q-hi fragments into registers (all ks steps), then free BUFA.
    const uint32_t q_lane_off = (uint32_t)(w * 16 + (lane & 15)) * 144 + ((lane >> 4) << 4);
    uint32_t qh_r[4][4];
#pragma unroll
    for (int ks = 0; ks < 4; ks++)
        ldm_x4(qh_r[ks], smb + FL_BUFA + q_lane_off + ks * 32);
    __syncthreads();                      // everyone done reading BUFA (Q-hi)

    const int ntiles = 2 * mT + 2;
    float m0 = -1e30f, m1 = -1e30f, l0 = 0.f, l1 = 0.f;
    float o[8][4];
#pragma unroll
    for (int nt = 0; nt < 8; nt++)
#pragma unroll
        for (int j = 0; j < 4; j++) o[nt][j] = 0.f;

    const int wr0 = mT * 128 + w * 16;    // warp's first global row
    const uint32_t k_row = (lane & 7);
    const uint32_t k_cb = ((lane >> 3) & 1) << 4;

    for (int kn = 0; kn < ntiles; kn++) {
        uint32_t kbuf = smb + ((kn & 1) ? FL_BUFA : FL_BUFB);
        if (kn + 1 < ntiles) {
            fl_load_kv(khp, klp, vhp, vlp, kn + 1,
                       smb + (((kn + 1) & 1) ? FL_BUFA : FL_BUFB), tid);
            CP_COMMIT();
            CP_WAIT(1);
        } else {
            CP_WAIT(0);
        }
        __syncthreads();

        if (64 * kn <= wr0 + 15) {        // otherwise fully above diagonal: skip
            // ---- S = Q @ K^T (3 split products; Q-hi from regs, Q-lo from smem) ----
            float s[8][4];
#pragma unroll
            for (int nt = 0; nt < 8; nt++)
#pragma unroll
                for (int j = 0; j < 4; j++) s[nt][j] = 0.f;

#pragma unroll
            for (int ks = 0; ks < 4; ks++) {
                uint32_t aql[4];
                ldm_x4(aql, smb + FL_QLO + q_lane_off + ks * 32);
#pragma unroll
                for (int nt = 0; nt < 8; nt++) {
                    uint32_t bkh[2], bkl[2];
                    uint32_t ka = kbuf + (nt * 8 + k_row) * 144 + ks * 32 + k_cb;
                    ldm_x2(bkh, ka);
                    ldm_x2(bkl, ka + 9216);
                    mma_bf16(s[nt], qh_r[ks], bkh);
                    mma_bf16(s[nt], qh_r[ks], bkl);
                    mma_bf16(s[nt], aql, bkh);
                }
            }

            // ---- scale + causal mask ----
            const bool needm = (64 * kn + 63 > wr0);
            const int rg0 = wr0 + (lane >> 2);
            const int rg1 = rg0 + 8;
            const int cbase = 64 * kn + 2 * (lane & 3);
#pragma unroll
            for (int nt = 0; nt < 8; nt++) {
                int c0 = cbase + 8 * nt;
#pragma unroll
                for (int j = 0; j < 4; j++) {
                    s[nt][j] *= 0.125f;
                    if (needm) {
                        int col = c0 + (j & 1);
                        int row = (j < 2) ? rg0 : rg1;
                        if (col > row) s[nt][j] = -1e30f;
                    }
                }
            }

            // ---- online softmax (rows rg0, rg1 per thread) ----
            float mx0 = -1e30f, mx1 = -1e30f;
#pragma unroll
            for (int nt = 0; nt < 8; nt++) {
                mx0 = fmaxf(mx0, fmaxf(s[nt][0], s[nt][1]));
                mx1 = fmaxf(mx1, fmaxf(s[nt][2], s[nt][3]));
            }
#pragma unroll
            for (int off = 1; off <= 2; off <<= 1) {
                mx0 = fmaxf(mx0, __shfl_xor_sync(0xffffffffu, mx0, off));
                mx1 = fmaxf(mx1, __shfl_xor_sync(0xffffffffu, mx1, off));
            }
            float mn0 = fmaxf(m0, mx0), mn1 = fmaxf(m1, mx1);
            float fac0 = __expf(m0 - mn0), fac1 = __expf(m1 - mn1);
            float ps0 = 0.f, ps1 = 0.f;
#pragma unroll
            for (int nt = 0; nt < 8; nt++) {
                s[nt][0] = __expf(s[nt][0] - mn0);
                s[nt][1] = __expf(s[nt][1] - mn0);
                s[nt][2] = __expf(s[nt][2] - mn1);
                s[nt][3] = __expf(s[nt][3] - mn1);
                ps0 += s[nt][0] + s[nt][1];
                ps1 += s[nt][2] + s[nt][3];
            }
#pragma unroll
            for (int off = 1; off <= 2; off <<= 1) {
                ps0 += __shfl_xor_sync(0xffffffffu, ps0, off);
                ps1 += __shfl_xor_sync(0xffffffffu, ps1, off);
            }
            l0 = l0 * fac0 + ps0;
            l1 = l1 * fac1 + ps1;
            m0 = mn0; m1 = mn1;
#pragma unroll
            for (int nt = 0; nt < 8; nt++) {
                o[nt][0] *= fac0; o[nt][1] *= fac0;
                o[nt][2] *= fac1; o[nt][3] *= fac1;
            }

            // ---- O += P @ V (3 split products; V B-frag via ldmatrix.trans) ----
#pragma unroll
            for (int ks = 0; ks < 4; ks++) {
                uint32_t ph[4], pl[4];
#pragma unroll
                for (int half = 0; half < 2; half++) {
                    const float* sv = s[2 * ks + half];
#pragma unroll
                    for (int rr = 0; rr < 2; rr++) {
                        float v0 = sv[2 * rr], v1 = sv[2 * rr + 1];
                        float h0 = __bfloat162float(__float2bfloat16(v0));
                        float h1 = __bfloat162float(__float2bfloat16(v1));
                        ph[half * 2 + rr] = pack_bf16(v0, v1);
                        pl[half * 2 + rr] = pack_bf16(v0 - h0, v1 - h1);
                    }
                }
#pragma unroll
                for (int nt = 0; nt < 8; nt++) {
                    uint32_t bvh[2], bvl[2];
                    uint32_t va = kbuf + 18432 +
                                  (uint32_t)(16 * ks + (lane & 15)) * 144 + nt * 16;
                    ldm_x2t(bvh, va);
                    ldm_x2t(bvl, va + 9216);
                    mma_bf16(o[nt], ph, bvh);
                    mma_bf16(o[nt], ph, bvl);
                    mma_bf16(o[nt], pl, bvh);
                }
            }
        }
        __syncthreads();
    }

    // ---- epilogue: write attn hi/lo in (B,S,H,D) ----
    float inv0 = 1.f / l0, inv1 = 1.f / l1;
    int gr0 = wr0 + (lane >> 2);
    size_t base0 = ((size_t)(b * 2048 + gr0)) * 2048 + h * 64;
    size_t base1 = base0 + (size_t)8 * 2048;
#pragma unroll
    for (int nt = 0; nt < 8; nt++) {
        int d0 = nt * 8 + 2 * (lane & 3);
        float v0 = o[nt][0] * inv0, v1 = o[nt][1] * inv0;
        float h0 = __bfloat162float(__float2bfloat16(v0));
        float h1 = __bfloat162float(__float2bfloat16(v1));
        *(uint32_t*)(Oh + base0 + d0) = pack_bf16(v0, v1);
        *(uint32_t*)(Ol + base0 + d0) = pack_bf16(v0 - h0, v1 - h1);
        float v2 = o[nt][2] * inv1, v3 = o[nt][3] * inv1;
        float h2 = __bfloat162float(__float2bfloat16(v2));
        float h3 = __bfloat162float(__float2bfloat16(v3));
        *(uint32_t*)(Oh + base1 + d0) = pack_bf16(v2, v3);
        *(uint32_t*)(Ol + base1 + d0) = pack_bf16(v2 - h2, v3 - h3);
    }
}

extern "C" void kernel_launch(void* const* d_in, const int* in_sizes, int n_in,
                              void* d_out, int out_size)
{
    const float* x    = (const float*)d_in[0];
    // d_in[1] = mask (deterministic causal triu) — computed analytically
    const float* cosx = (const float*)d_in[2];
    const float* sinx = (const float*)d_in[3];
    const float* Wq   = (const float*)d_in[4];
    const float* Wk   = (const float*)d_in[5];
    const float* Wv   = (const float*)d_in[6];
    const float* Wo   = (const float*)d_in[7];

    float* out  = (float*)d_out;          // (B,S,E)
    float* outK = out + 8388608;          // (B,KV,S,D)
    float* outV = outK + 2097152;

    float *qproj, *kproj, *vproj;
    cudaGetSymbolAddress((void**)&qproj, g_qproj);
    cudaGetSymbolAddress((void**)&kproj, g_kproj);
    cudaGetSymbolAddress((void**)&vproj, g_vproj);

    __nv_bfloat16 *qrh, *qrl, *khi, *klo, *vhi, *vlo;
    cudaGetSymbolAddress((void**)&qrh, g_qrh);
    cudaGetSymbolAddress((void**)&qrl, g_qrl);
    cudaGetSymbolAddress((void**)&khi, g_khi);
    cudaGetSymbolAddress((void**)&klo, g_klo);
    cudaGetSymbolAddress((void**)&vhi, g_vhi);
    cudaGetSymbolAddress((void**)&vlo, g_vlo);

    __nv_bfloat16 *xhi, *xlo, *ahi, *alo;
    __nv_bfloat16 *wqh, *wql, *wkh, *wkl, *wvh, *wvl, *woh, *wol;
    cudaGetSymbolAddress((void**)&xhi, g_xhi);
    cudaGetSymbolAddress((void**)&xlo, g_xlo);
    cudaGetSymbolAddress((void**)&ahi, g_ahi);
    cudaGetSymbolAddress((void**)&alo, g_alo);
    cudaGetSymbolAddress((void**)&wqh, g_wqt_hi);
    cudaGetSymbolAddress((void**)&wql, g_wqt_lo);
    cudaGetSymbolAddress((void**)&wkh, g_wkt_hi);
    cudaGetSymbolAddress((void**)&wkl, g_wkt_lo);
    cudaGetSymbolAddress((void**)&wvh, g_wvt_hi);
    cudaGetSymbolAddress((void**)&wvl, g_wvt_lo);
    cudaGetSymbolAddress((void**)&woh, g_wot_hi);
    cudaGetSymbolAddress((void**)&wol, g_wot_lo);

    cudaFuncSetAttribute(gemm_mma_kernel,
                         cudaFuncAttributeMaxDynamicSharedMemorySize, GEMM_SMEM);
    cudaFuncSetAttribute(gemm_qkv_kernel,
                         cudaFuncAttributeMaxDynamicSharedMemorySize, GEMM_SMEM);
    cudaFuncSetAttribute(flash_mma_kernel,
                         cudaFuncAttributeMaxDynamicSharedMemorySize, FL_SMEM);

    dim3 blk(256);
    dim3 tblk(32, 8);

    // Preprocess: split x; transpose+split weights
    split_kernel<<<8388608 / 256, blk>>>(x, xhi, xlo);
    transpose_split_kernel<<<dim3(64, 64), tblk>>>(Wq, wqh, wql, 2048, 2048);
    transpose_split_kernel<<<dim3(16, 64), tblk>>>(Wk, wkh, wkl, 2048, 512);
    transpose_split_kernel<<<dim3(16, 64), tblk>>>(Wv, wvh, wvl, 2048, 512);
    transpose_split_kernel<<<dim3(64, 64), tblk>>>(Wo, woh, wol, 2048, 2048);

    // Fused QKV projections (tensor cores, split-precision)
    gemm_qkv_kernel<<<dim3(24, 32), blk, GEMM_SMEM>>>(
        xhi, xlo, wqh, wql, wkh, wkl, wvh, wvl, qproj, kproj, vproj);

    // RoPE + layout transforms (fp32 K/V straight into d_out, bf16 hi/lo for attn)
    rope_q_kernel<<<8388608 / 256, 256>>>(qproj, cosx, sinx, qrh, qrl);
    rope_kv_kernel<<<2097152 / 256, 256>>>(kproj, vproj, cosx, sinx,
                                           outK, outV, khi, klo, vhi, vlo);

    // Flash attention on tensor cores (split-precision), emits hi/lo directly
    flash_mma_kernel<<<dim3(16, 64), blk, FL_SMEM>>>(
        qrh, qrl, khi, klo, vhi, vlo, ahi, alo);

    // Output projection
    gemm_mma_kernel<<<dim3(16, 32), blk, GEMM_SMEM>>>(
        ahi, alo, woh, wol, out, 4096, 2048, 2048);
}

// round 8
// speedup vs baseline: 3.0686x; 1.0122x over previous
#include <cuda_runtime.h>
#include <cuda_bf16.h>
#include <math.h>
#include <stdint.h>

// Problem constants: B=2, S=2048, E=2048, NH=32, NKV=8, HD=64, GROUP=4, M=B*S=4096

// -------- scratch (static device globals; allocation-free) --------
__device__ float g_qproj[4096 * 2048];
__device__ float g_kproj[4096 * 512];
__device__ float g_vproj[4096 * 512];

__device__ __nv_bfloat16 g_qrh[4096 * 2048];   // roped Q hi (B,H,S,D)
__device__ __nv_bfloat16 g_qrl[4096 * 2048];   // roped Q lo
__device__ __nv_bfloat16 g_khi[2097152];       // roped K hi (B,KV,S,D)
__device__ __nv_bfloat16 g_klo[2097152];
__device__ __nv_bfloat16 g_vhi[2097152];
__device__ __nv_bfloat16 g_vlo[2097152];

__device__ __nv_bfloat16 g_xhi[4096 * 2048];
__device__ __nv_bfloat16 g_xlo[4096 * 2048];
__device__ __nv_bfloat16 g_ahi[4096 * 2048];   // attn out hi (B,S,H,D)
__device__ __nv_bfloat16 g_alo[4096 * 2048];
__device__ __nv_bfloat16 g_wqt_hi[2048 * 2048];
__device__ __nv_bfloat16 g_wqt_lo[2048 * 2048];
__device__ __nv_bfloat16 g_wkt_hi[512 * 2048];
__device__ __nv_bfloat16 g_wkt_lo[512 * 2048];
__device__ __nv_bfloat16 g_wvt_hi[512 * 2048];
__device__ __nv_bfloat16 g_wvt_lo[512 * 2048];
__device__ __nv_bfloat16 g_wot_hi[2048 * 2048];
__device__ __nv_bfloat16 g_wot_lo[2048 * 2048];

// ================= PTX helpers (compute_103-safe) =================
__device__ __forceinline__ uint32_t smem_u32(const void* p) {
    uint32_t a;
    asm("{ .reg .u64 t; cvta.to.shared.u64 t, %1; cvt.u32.u64 %0, t; }" : "=r"(a) : "l"(p));
    return a;
}
__device__ __forceinline__ void cp_async16(uint32_t dst, const void* src) {
    asm volatile("cp.async.cg.shared.global [%0], [%1], 16;" :: "r"(dst), "l"(src));
}
#define CP_COMMIT() asm volatile("cp.async.commit_group;" ::: "memory")
#define CP_WAIT(n)  asm volatile("cp.async.wait_group %0;" :: "n"(n) : "memory")

__device__ __forceinline__ void ldm_x4(uint32_t* r, uint32_t addr) {
    asm volatile("ldmatrix.sync.aligned.m8n8.x4.shared.b16 {%0,%1,%2,%3}, [%4];"
                 : "=r"(r[0]), "=r"(r[1]), "=r"(r[2]), "=r"(r[3]) : "r"(addr));
}
__device__ __forceinline__ void ldm_x2(uint32_t* r, uint32_t addr) {
    asm volatile("ldmatrix.sync.aligned.m8n8.x2.shared.b16 {%0,%1}, [%2];"
                 : "=r"(r[0]), "=r"(r[1]) : "r"(addr));
}
__device__ __forceinline__ void ldm_x2t(uint32_t* r, uint32_t addr) {
    asm volatile("ldmatrix.sync.aligned.m8n8.x2.trans.shared.b16 {%0,%1}, [%2];"
                 : "=r"(r[0]), "=r"(r[1]) : "r"(addr));
}
__device__ __forceinline__ void mma_bf16(float* c, const uint32_t* a, const uint32_t* b) {
    asm volatile(
        "mma.sync.aligned.m16n8k16.row.col.f32.bf16.bf16.f32 "
        "{%0,%1,%2,%3}, {%4,%5,%6,%7}, {%8,%9}, {%0,%1,%2,%3};"
        : "+f"(c[0]), "+f"(c[1]), "+f"(c[2]), "+f"(c[3])
        : "r"(a[0]), "r"(a[1]), "r"(a[2]), "r"(a[3]), "r"(b[0]), "r"(b[1]));
}
// pack two fp32 into bf16x2: first arg -> low half, second -> high half
__device__ __forceinline__ uint32_t pack_bf16(float lo, float hi) {
    uint32_t r;
    asm("cvt.rn.bf16x2.f32 %0, %1, %2;" : "=r"(r) : "f"(hi), "f"(lo));
    return r;
}

// ================= elementwise split fp32 -> bf16 hi/lo (vectorized x4) =================
__global__ __launch_bounds__(256) void split_kernel(
    const float* __restrict__ src, __nv_bfloat16* __restrict__ hi,
    __nv_bfloat16* __restrict__ lo)
{
    int i = blockIdx.x * 256 + threadIdx.x;
    float4 v = ((const float4*)src)[i];
    float h0 = __bfloat162float(__float2bfloat16(v.x));
    float h1 = __bfloat162float(__float2bfloat16(v.y));
    float h2 = __bfloat162float(__float2bfloat16(v.z));
    float h3 = __bfloat162float(__float2bfloat16(v.w));
    uint2 hv = make_uint2(pack_bf16(v.x, v.y), pack_bf16(v.z, v.w));
    uint2 lv = make_uint2(pack_bf16(v.x - h0, v.y - h1), pack_bf16(v.z - h2, v.w - h3));
    ((uint2*)hi)[i] = hv;
    ((uint2*)lo)[i] = lv;
}

// ============ weight transpose + split: W(K x N) -> WT_hi/lo (N x K) ============
__global__ __launch_bounds__(256) void transpose_split_kernel(
    const float* __restrict__ W, __nv_bfloat16* __restrict__ hi,
    __nv_bfloat16* __restrict__ lo, int K, int N)
{
    __shared__ float t[32][33];
    int n0 = blockIdx.x * 32, k0 = blockIdx.y * 32;
    int tx = threadIdx.x, ty = threadIdx.y;   // 32 x 8
#pragma unroll
    for (int i = 0; i < 32; i += 8)
        t[ty + i][tx] = W[(size_t)(k0 + ty + i) * N + n0 + tx];
    __syncthreads();
#pragma unroll
    for (int i = 0; i < 32; i += 8) {
        float v = t[tx][ty + i];
        __nv_bfloat16 h = __float2bfloat16(v);
        size_t o = (size_t)(n0 + ty + i) * K + k0 + tx;
        hi[o] = h;
        lo[o] = __float2bfloat16(v - __bfloat162float(h));
    }
}

// ================= mma.sync split-bf16 GEMM (256x128 CTA tile) =================
// C(MxN) fp32 = A(MxK) @ B^T with A hi/lo (M,K), B hi/lo (N,K) K-major.
// 256x128 CTA tile, BK=32, double-buffered cp.async, 512 threads = 16 warps
// (4m x 4n), warp tile 64x32. Rows padded 32 bf16 -> 40 (80B stride).
static const int GA_TILE = 256 * 80;             // 20480 B per A variant
static const int GB_TILE = 128 * 80;             // 10240 B per B variant
static const int GBUF    = 2 * GA_TILE + 2 * GB_TILE;   // 61440 B per buffer
static const int GEMM_SMEM = 2 * GBUF;           // 122880 B

__device__ __forceinline__ void load_chunk(
    const __nv_bfloat16* __restrict__ Ahi, const __nv_bfloat16* __restrict__ Alo,
    const __nv_bfloat16* __restrict__ Bhi, const __nv_bfloat16* __restrict__ Blo,
    int m0, int n0, int k0, int K, uint32_t smbuf, int tid)
{
    const __nv_bfloat16* ah = Ahi + (size_t)m0 * K + k0;
    const __nv_bfloat16* al = Alo + (size_t)m0 * K + k0;
    const __nv_bfloat16* bh = Bhi + (size_t)n0 * K + k0;
    const __nv_bfloat16* bl = Blo + (size_t)n0 * K + k0;
#pragma unroll
    for (int v = 0; v < 2; v++) {                // A: 1024 16B vectors each
        int idx = v * 512 + tid;
        int row = idx >> 2, c16 = idx & 3;
        uint32_t off = (uint32_t)row * 80 + c16 * 16;
        cp_async16(smbuf + off, ah + (size_t)row * K + c16 * 8);
        cp_async16(smbuf + GA_TILE + off, al + (size_t)row * K + c16 * 8);
    }
    {                                            // B: 512 vectors each
        int row = tid >> 2, c16 = tid & 3;
        uint32_t off = (uint32_t)row * 80 + c16 * 16;
        cp_async16(smbuf + 2 * GA_TILE + off, bh + (size_t)row * K + c16 * 8);
        cp_async16(smbuf + 2 * GA_TILE + GB_TILE + off, bl + (size_t)row * K + c16 * 8);
    }
}

__device__ __forceinline__ void gemm_body(
    const __nv_bfloat16* __restrict__ Ahi, const __nv_bfloat16* __restrict__ Alo,
    const __nv_bfloat16* __restrict__ Bhi, const __nv_bfloat16* __restrict__ Blo,
    float* __restrict__ C, int m0, int n0, int N, int K, uint32_t smb)
{
    const int tid = threadIdx.x;
    const int lane = tid & 31, wid = tid >> 5;
    const int warp_m = wid >> 2;                 // 0..3 -> m offset *64
    const int warp_n = wid & 3;                  // 0..3 -> n offset *32

    float acc[4][4][4];
#pragma unroll
    for (int i = 0; i < 4; i++)
#pragma unroll
        for (int j = 0; j < 4; j++)
#pragma unroll
            for (int r = 0; r < 4; r++) acc[i][j][r] = 0.f;

    const int nc = K >> 5;
    load_chunk(Ahi, Alo, Bhi, Blo, m0, n0, 0, K, smb, tid);
    CP_COMMIT();

    const int a_row = warp_m * 64 + (lane & 15);
    const int a_colb = ((lane >> 4) << 3) * 2;
    const int b_row = warp_n * 32 + (lane & 7);
    const int b_colb = (((lane >> 3) & 1) << 3) * 2;

    for (int c = 0; c < nc; c++) {
        uint32_t buf = smb + (c & 1) * GBUF;
        if (c + 1 < nc) {
            load_chunk(Ahi, Alo, Bhi, Blo, m0, n0, (c + 1) << 5, K,
                       smb + ((c + 1) & 1) * GBUF, tid);
            CP_COMMIT();
            CP_WAIT(1);
        } else {
            CP_WAIT(0);
        }
        __syncthreads();

#pragma unroll
        for (int ks = 0; ks < 2; ks++) {
            const int ksb = ks * 32;
            uint32_t bh4[4][2], bl4[4][2];
#pragma unroll
            for (int nt = 0; nt < 4; nt++) {
                uint32_t rowoff = (uint32_t)(b_row + nt * 8) * 80 + ksb + b_colb;
                ldm_x2(bh4[nt], buf + 2 * GA_TILE + rowoff);
                ldm_x2(bl4[nt], buf + 2 * GA_TILE + GB_TILE + rowoff);
            }
#pragma unroll
            for (int mt = 0; mt < 4; mt++) {
                uint32_t ah4[4], al4[4];
                uint32_t rowoff = (uint32_t)(a_row + mt * 16) * 80 + ksb + a_colb;
                ldm_x4(ah4, buf + rowoff);
                ldm_x4(al4, buf + GA_TILE + rowoff);
#pragma unroll
                for (int nt = 0; nt < 4; nt++) {
                    mma_bf16(acc[mt][nt], ah4, bh4[nt]);
                    mma_bf16(acc[mt][nt], ah4, bl4[nt]);
                    mma_bf16(acc[mt][nt], al4, bh4[nt]);
                }
            }
        }
        __syncthreads();
    }

    const int cm = lane >> 2, cn = (lane & 3) << 1;
#pragma unroll
    for (int mt = 0; mt < 4; mt++) {
        int gm = m0 + warp_m * 64 + mt * 16 + cm;
#pragma unroll
        for (int nt = 0; nt < 4; nt++) {
            int gn = n0 + warp_n * 32 + nt * 8 + cn;
            float* cp0 = C + (size_t)gm * N + gn;
            cp0[0] = acc[mt][nt][0];
            cp0[1] = acc[mt][nt][1];
            float* cp1 = C + (size_t)(gm + 8) * N + gn;
            cp1[0] = acc[mt][nt][2];
            cp1[1] = acc[mt][nt][3];
        }
    }
}

__global__ __launch_bounds__(512, 1) void gemm_mma_kernel(
    const __nv_bfloat16* __restrict__ Ahi, const __nv_bfloat16* __restrict__ Alo,
    const __nv_bfloat16* __restrict__ Bhi, const __nv_bfloat16* __restrict__ Blo,
    float* __restrict__ C, int M, int N, int K)
{
    extern __shared__ char sm[];
    gemm_body(Ahi, Alo, Bhi, Blo, C, blockIdx.y * 256, blockIdx.x * 128, N, K,
              smem_u32(sm));
}

// fused QKV projection: grid.x = 24 (16 Q col-tiles, 4 K, 4 V), grid.y = 16
__global__ __launch_bounds__(512, 1) void gemm_qkv_kernel(
    const __nv_bfloat16* __restrict__ xhi, const __nv_bfloat16* __restrict__ xlo,
    const __nv_bfloat16* __restrict__ wqh, const __nv_bfloat16* __restrict__ wql,
    const __nv_bfloat16* __restrict__ wkh, const __nv_bfloat16* __restrict__ wkl,
    const __nv_bfloat16* __restrict__ wvh, const __nv_bfloat16* __restrict__ wvl,
    float* __restrict__ qp, float* __restrict__ kp, float* __restrict__ vp)
{
    extern __shared__ char sm[];
    int bx = blockIdx.x;
    const __nv_bfloat16 *bh_, *bl_;
    float* C;
    int N, n0;
    if (bx < 16)      { bh_ = wqh; bl_ = wql; C = qp; N = 2048; n0 = bx * 128; }
    else if (bx < 20) { bh_ = wkh; bl_ = wkl; C = kp; N = 512;  n0 = (bx - 16) * 128; }
    else              { bh_ = wvh; bl_ = wvl; C = vp; N = 512;  n0 = (bx - 20) * 128; }
    gemm_body(xhi, xlo, bh_, bl_, C, blockIdx.y * 256, n0, N, 2048, smem_u32(sm));
}

// ------- RoPE on Q: (B,S,H,D) proj -> (B,H,S,D) bf16 hi/lo; one thread = (d, d+32) pair -------
__global__ __launch_bounds__(256) void rope_q_kernel(
    const float* __restrict__ qp, const float* __restrict__ cosx,
    const float* __restrict__ sinx, __nv_bfloat16* __restrict__ qh,
    __nv_bfloat16* __restrict__ ql)
{
    int i = blockIdx.x * blockDim.x + threadIdx.x;   // (b,h,s,d32)
    int d = i & 31;
    int s = (i >> 5) & 2047;
    int h = (i >> 16) & 31;
    int b = i >> 21;
    size_t src = ((size_t)(b * 2048 + s)) * 2048 + h * 64;
    float v1 = qp[src + d];
    float v2 = qp[src + d + 32];
    float c1 = cosx[s * 64 + d],      s1 = sinx[s * 64 + d];
    float c2 = cosx[s * 64 + d + 32], s2 = sinx[s * 64 + d + 32];
    float o1 = v1 * c1 - v2 * s1;
    float o2 = v2 * c2 + v1 * s2;
    size_t dst = ((size_t)((b * 32 + h) * 2048 + s)) * 64 + d;
    float h1 = __bfloat162float(__float2bfloat16(o1));
    float h2 = __bfloat162float(__float2bfloat16(o2));
    qh[dst]      = __float2bfloat16(o1);
    qh[dst + 32] = __float2bfloat16(o2);
    ql[dst]      = __float2bfloat16(o1 - h1);
    ql[dst + 32] = __float2bfloat16(o2 - h2);
}

// ---- RoPE K + copy V: fp32 into d_out (required) + bf16 hi/lo; (d, d+32) pairs ----
__global__ __launch_bounds__(256) void rope_kv_kernel(
    const float* __restrict__ kp, const float* __restrict__ vp,
    const float* __restrict__ cosx, const float* __restrict__ sinx,
    float* __restrict__ ko, float* __restrict__ vo,
    __nv_bfloat16* __restrict__ kh, __nv_bfloat16* __restrict__ kl,
    __nv_bfloat16* __restrict__ vh, __nv_bfloat16* __restrict__ vl)
{
    int i = blockIdx.x * blockDim.x + threadIdx.x;   // (b,kv,s,d32)
    int d = i & 31;
    int s = (i >> 5) & 2047;
    int kv = (i >> 16) & 7;
    int b = i >> 19;
    size_t src = ((size_t)(b * 2048 + s)) * 512 + kv * 64;
    float v1 = kp[src + d];
    float v2 = kp[src + d + 32];
    float c1 = cosx[s * 64 + d],      s1 = sinx[s * 64 + d];
    float c2 = cosx[s * 64 + d + 32], s2 = sinx[s * 64 + d + 32];
    float k1 = v1 * c1 - v2 * s1;
    float k2 = v2 * c2 + v1 * s2;
    float w1 = vp[src + d];
    float w2 = vp[src + d + 32];
    size_t dst = ((size_t)((b * 8 + kv) * 2048 + s)) * 64 + d;
    ko[dst] = k1;      ko[dst + 32] = k2;
    vo[dst] = w1;      vo[dst + 32] = w2;
    float kh1 = __bfloat162float(__float2bfloat16(k1));
    float kh2 = __bfloat162float(__float2bfloat16(k2));
    kh[dst]      = __float2bfloat16(k1);
    kh[dst + 32] = __float2bfloat16(k2);
    kl[dst]      = __float2bfloat16(k1 - kh1);
    kl[dst + 32] = __float2bfloat16(k2 - kh2);
    float vh1 = __bfloat162float(__float2bfloat16(w1));
    float vh2 = __bfloat162float(__float2bfloat16(w2));
    vh[dst]      = __float2bfloat16(w1);
    vh[dst + 32] = __float2bfloat16(w2);
    vl[dst]      = __float2bfloat16(w1 - vh1);
    vl[dst + 32] = __float2bfloat16(w2 - vh2);
}

// ---------------- Flash attention: mma.sync bf16 split-precision ----------------
// Q tile 128 rows, KV tiles 64. 8 warps; warp owns 16 Q rows.
// Q-hi fragments in registers; Q-lo in smem. Smem rows padded to 144 B.
//   [0, 18432)        Q-lo (persistent)
//   [18432, 55296)    KV buffer A ({Kh,Kl,Vh,Vl} x 9216) -- Q-hi staging at start
//   [55296, 92160)    KV buffer B
static const int FL_QLO  = 0;
static const int FL_BUFA = 18432;
static const int FL_BUFB = 55296;
static const int FL_SMEM = 92160;

__device__ __forceinline__ void fl_load_kv(
    const __nv_bfloat16* kh, const __nv_bfloat16* kl,
    const __nv_bfloat16* vh, const __nv_bfloat16* vl,
    int kn, uint32_t bufb, int tid)
{
    const __nv_bfloat16* srcs[4] = { kh + kn * 64 * 64, kl + kn * 64 * 64,
                                     vh + kn * 64 * 64, vl + kn * 64 * 64 };
#pragma unroll
    for (int t = 0; t < 4; t++) {
        uint32_t dstb = bufb + t * 9216;
#pragma unroll
        for (int v = 0; v < 2; v++) {
            int idx = v * 256 + tid;
            int row = idx >> 3, c16 = idx & 7;
            cp_async16(dstb + row * 144 + c16 * 16, srcs[t] + row * 64 + c16 * 8);
        }
    }
}

__global__ __launch_bounds__(256, 2) void flash_mma_kernel(
    const __nv_bfloat16* __restrict__ Qh, const __nv_bfloat16* __restrict__ Ql,
    const __nv_bfloat16* __restrict__ Kh, const __nv_bfloat16* __restrict__ Kl,
    const __nv_bfloat16* __restrict__ Vh, const __nv_bfloat16* __restrict__ Vl,
    __nv_bfloat16* __restrict__ Oh, __nv_bfloat16* __restrict__ Ol)
{
    extern __shared__ char sm[];
    uint32_t smb = smem_u32(sm);
    const int tid = threadIdx.x, lane = tid & 31, w = tid >> 5;
    const int mT = 15 - blockIdx.x;
    const int bh = blockIdx.y;
    const int b = bh >> 5, h = bh & 31, kvh = h >> 2;

    const __nv_bfloat16* qh = Qh + ((size_t)bh * 2048 + mT * 128) * 64;
    const __nv_bfloat16* qlp = Ql + ((size_t)bh * 2048 + mT * 128) * 64;
    const size_t kvoff = (size_t)(b * 8 + kvh) * 2048 * 64;
    const __nv_bfloat16* khp = Kh + kvoff;
    const __nv_bfloat16* klp = Kl + kvoff;
    const __nv_bfloat16* vhp = Vh + kvoff;
    const __nv_bfloat16* vlp = Vl + kvoff;

#pragma unroll
    for (int v = 0; v < 4; v++) {
        int idx = v * 256 + tid;
        int row = idx >> 3, c16 = idx & 7;
        cp_async16(smb + FL_BUFA + row * 144 + c16 * 16, qh + row * 64 + c16 * 8);
        cp_async16(smb + FL_QLO + row * 144 + c16 * 16, qlp + row * 64 + c16 * 8);
    }
    CP_COMMIT();
    fl_load_kv(khp, klp, vhp, vlp, 0, smb + FL_BUFB, tid);
    CP_COMMIT();
    CP_WAIT(1);
    __syncthreads();

    const uint32_t q_lane_off = (uint32_t)(w * 16 + (lane & 15)) * 144 + ((lane >> 4) << 4);
    uint32_t qh_r[4][4];
#pragma unroll
    for (int ks = 0; ks < 4; ks++)
        ldm_x4(qh_r[ks], smb + FL_BUFA + q_lane_off + ks * 32);
    __syncthreads();

    const int ntiles = 2 * mT + 2;
    float m0 = -1e30f, m1 = -1e30f, l0 = 0.f, l1 = 0.f;
    float o[8][4];
#pragma unroll
    for (int nt = 0; nt < 8; nt++)
#pragma unroll
        for (int j = 0; j < 4; j++) o[nt][j] = 0.f;

    const int wr0 = mT * 128 + w * 16;
    const uint32_t k_row = (lane & 7);
    const uint32_t k_cb = ((lane >> 3) & 1) << 4;

    for (int kn = 0; kn < ntiles; kn++) {
        uint32_t kbuf = smb + ((kn & 1) ? FL_BUFA : FL_BUFB);
        if (kn + 1 < ntiles) {
            fl_load_kv(khp, klp, vhp, vlp, kn + 1,
                       smb + (((kn + 1) & 1) ? FL_BUFA : FL_BUFB), tid);
            CP_COMMIT();
            CP_WAIT(1);
        } else {
            CP_WAIT(0);
        }
        __syncthreads();

        if (64 * kn <= wr0 + 15) {
            float s[8][4];
#pragma unroll
            for (int nt = 0; nt < 8; nt++)
#pragma unroll
                for (int j = 0; j < 4; j++) s[nt][j] = 0.f;

#pragma unroll
            for (int ks = 0; ks < 4; ks++) {
                uint32_t aql[4];
                ldm_x4(aql, smb + FL_QLO + q_lane_off + ks * 32);
#pragma unroll
                for (int nt = 0; nt < 8; nt++) {
                    uint32_t bkh[2], bkl[2];
                    uint32_t ka = kbuf + (nt * 8 + k_row) * 144 + ks * 32 + k_cb;
                    ldm_x2(bkh, ka);
                    ldm_x2(bkl, ka + 9216);
                    mma_bf16(s[nt], qh_r[ks], bkh);
                    mma_bf16(s[nt], qh_r[ks], bkl);
                    mma_bf16(s[nt], aql, bkh);
                }
            }

            const bool needm = (64 * kn + 63 > wr0);
            const int rg0 = wr0 + (lane >> 2);
            const int rg1 = rg0 + 8;
            const int cbase = 64 * kn + 2 * (lane & 3);
#pragma unroll
            for (int nt = 0; nt < 8; nt++) {
                int c0 = cbase + 8 * nt;
#pragma unroll
                for (int j = 0; j < 4; j++) {
                    s[nt][j] *= 0.125f;
                    if (needm) {
                        int col = c0 + (j & 1);
                        int row = (j < 2) ? rg0 : rg1;
                        if (col > row) s[nt][j] = -1e30f;
                    }
                }
            }

            float mx0 = -1e30f, mx1 = -1e30f;
#pragma unroll
            for (int nt = 0; nt < 8; nt++) {
                mx0 = fmaxf(mx0, fmaxf(s[nt][0], s[nt][1]));
                mx1 = fmaxf(mx1, fmaxf(s[nt][2], s[nt][3]));
            }
#pragma unroll
            for (int off = 1; off <= 2; off <<= 1) {
                mx0 = fmaxf(mx0, __shfl_xor_sync(0xffffffffu, mx0, off));
                mx1 = fmaxf(mx1, __shfl_xor_sync(0xffffffffu, mx1, off));
            }
            float mn0 = fmaxf(m0, mx0), mn1 = fmaxf(m1, mx1);
            float fac0 = __expf(m0 - mn0), fac1 = __expf(m1 - mn1);
            float ps0 = 0.f, ps1 = 0.f;
#pragma unroll
            for (int nt = 0; nt < 8; nt++) {
                s[nt][0] = __expf(s[nt][0] - mn0);
                s[nt][1] = __expf(s[nt][1] - mn0);
                s[nt][2] = __expf(s[nt][2] - mn1);
                s[nt][3] = __expf(s[nt][3] - mn1);
                ps0 += s[nt][0] + s[nt][1];
                ps1 += s[nt][2] + s[nt][3];
            }
#pragma unroll
            for (int off = 1; off <= 2; off <<= 1) {
                ps0 += __shfl_xor_sync(0xffffffffu, ps0, off);
                ps1 += __shfl_xor_sync(0xffffffffu, ps1, off);
            }
            l0 = l0 * fac0 + ps0;
            l1 = l1 * fac1 + ps1;
            m0 = mn0; m1 = mn1;
#pragma unroll
            for (int nt = 0; nt < 8; nt++) {
                o[nt][0] *= fac0; o[nt][1] *= fac0;
                o[nt][2] *= fac1; o[nt][3] *= fac1;
            }

#pragma unroll
            for (int ks = 0; ks < 4; ks++) {
                uint32_t ph[4], pl[4];
#pragma unroll
                for (int half = 0; half < 2; half++) {
                    const float* sv = s[2 * ks + half];
#pragma unroll
                    for (int rr = 0; rr < 2; rr++) {
                        float v0 = sv[2 * rr], v1 = sv[2 * rr + 1];
                        float h0 = __bfloat162float(__float2bfloat16(v0));
                        float h1 = __bfloat162float(__float2bfloat16(v1));
                        ph[half * 2 + rr] = pack_bf16(v0, v1);
                        pl[half * 2 + rr] = pack_bf16(v0 - h0, v1 - h1);
                    }
                }
#pragma unroll
                for (int nt = 0; nt < 8; nt++) {
                    uint32_t bvh[2], bvl[2];
                    uint32_t va = kbuf + 18432 +
                                  (uint32_t)(16 * ks + (lane & 15)) * 144 + nt * 16;
                    ldm_x2t(bvh, va);
                    ldm_x2t(bvl, va + 9216);
                    mma_bf16(o[nt], ph, bvh);
                    mma_bf16(o[nt], ph, bvl);
                    mma_bf16(o[nt], pl, bvh);
                }
            }
        }
        __syncthreads();
    }

    float inv0 = 1.f / l0, inv1 = 1.f / l1;
    int gr0 = wr0 + (lane >> 2);
    size_t base0 = ((size_t)(b * 2048 + gr0)) * 2048 + h * 64;
    size_t base1 = base0 + (size_t)8 * 2048;
#pragma unroll
    for (int nt = 0; nt < 8; nt++) {
        int d0 = nt * 8 + 2 * (lane & 3);
        float v0 = o[nt][0] * inv0, v1 = o[nt][1] * inv0;
        float h0 = __bfloat162float(__float2bfloat16(v0));
        float h1 = __bfloat162float(__float2bfloat16(v1));
        *(uint32_t*)(Oh + base0 + d0) = pack_bf16(v0, v1);
        *(uint32_t*)(Ol + base0 + d0) = pack_bf16(v0 - h0, v1 - h1);
        float v2 = o[nt][2] * inv1, v3 = o[nt][3] * inv1;
        float h2 = __bfloat162float(__float2bfloat16(v2));
        float h3 = __bfloat162float(__float2bfloat16(v3));
        *(uint32_t*)(Oh + base1 + d0) = pack_bf16(v2, v3);
        *(uint32_t*)(Ol + base1 + d0) = pack_bf16(v2 - h2, v3 - h3);
    }
}

extern "C" void kernel_launch(void* const* d_in, const int* in_sizes, int n_in,
                              void* d_out, int out_size)
{
    const float* x    = (const float*)d_in[0];
    // d_in[1] = mask (deterministic causal triu) — computed analytically
    const float* cosx = (const float*)d_in[2];
    const float* sinx = (const float*)d_in[3];
    const float* Wq   = (const float*)d_in[4];
    const float* Wk   = (const float*)d_in[5];
    const float* Wv   = (const float*)d_in[6];
    const float* Wo   = (const float*)d_in[7];

    float* out  = (float*)d_out;          // (B,S,E)
    float* outK = out + 8388608;          // (B,KV,S,D)
    float* outV = outK + 2097152;

    float *qproj, *kproj, *vproj;
    cudaGetSymbolAddress((void**)&qproj, g_qproj);
    cudaGetSymbolAddress((void**)&kproj, g_kproj);
    cudaGetSymbolAddress((void**)&vproj, g_vproj);

    __nv_bfloat16 *qrh, *qrl, *khi, *klo, *vhi, *vlo;
    cudaGetSymbolAddress((void**)&qrh, g_qrh);
    cudaGetSymbolAddress((void**)&qrl, g_qrl);
    cudaGetSymbolAddress((void**)&khi, g_khi);
    cudaGetSymbolAddress((void**)&klo, g_klo);
    cudaGetSymbolAddress((void**)&vhi, g_vhi);
    cudaGetSymbolAddress((void**)&vlo, g_vlo);

    __nv_bfloat16 *xhi, *xlo, *ahi, *alo;
    __nv_bfloat16 *wqh, *wql, *wkh, *wkl, *wvh, *wvl, *woh, *wol;
    cudaGetSymbolAddress((void**)&xhi, g_xhi);
    cudaGetSymbolAddress((void**)&xlo, g_xlo);
    cudaGetSymbolAddress((void**)&ahi, g_ahi);
    cudaGetSymbolAddress((void**)&alo, g_alo);
    cudaGetSymbolAddress((void**)&wqh, g_wqt_hi);
    cudaGetSymbolAddress((void**)&wql, g_wqt_lo);
    cudaGetSymbolAddress((void**)&wkh, g_wkt_hi);
    cudaGetSymbolAddress((void**)&wkl, g_wkt_lo);
    cudaGetSymbolAddress((void**)&wvh, g_wvt_hi);
    cudaGetSymbolAddress((void**)&wvl, g_wvt_lo);
    cudaGetSymbolAddress((void**)&woh, g_wot_hi);
    cudaGetSymbolAddress((void**)&wol, g_wot_lo);

    cudaFuncSetAttribute(gemm_mma_kernel,
                         cudaFuncAttributeMaxDynamicSharedMemorySize, GEMM_SMEM);
    cudaFuncSetAttribute(gemm_qkv_kernel,
                         cudaFuncAttributeMaxDynamicSharedMemorySize, GEMM_SMEM);
    cudaFuncSetAttribute(flash_mma_kernel,
                         cudaFuncAttributeMaxDynamicSharedMemorySize, FL_SMEM);

    dim3 tblk(32, 8);

    // Preprocess: split x (float4); transpose+split weights
    split_kernel<<<8192, 256>>>(x, xhi, xlo);
    transpose_split_kernel<<<dim3(64, 64), tblk>>>(Wq, wqh, wql, 2048, 2048);
    transpose_split_kernel<<<dim3(16, 64), tblk>>>(Wk, wkh, wkl, 2048, 512);
    transpose_split_kernel<<<dim3(16, 64), tblk>>>(Wv, wvh, wvl, 2048, 512);
    transpose_split_kernel<<<dim3(64, 64), tblk>>>(Wo, woh, wol, 2048, 2048);

    // Fused QKV projections (256-row tiles, 512 threads)
    gemm_qkv_kernel<<<dim3(24, 16), 512, GEMM_SMEM>>>(
        xhi, xlo, wqh, wql, wkh, wkl, wvh, wvl, qproj, kproj, vproj);

    // RoPE + layout transforms (pair-processing)
    rope_q_kernel<<<4194304 / 256, 256>>>(qproj, cosx, sinx, qrh, qrl);
    rope_kv_kernel<<<1048576 / 256, 256>>>(kproj, vproj, cosx, sinx,
                                           outK, outV, khi, klo, vhi, vlo);

    // Flash attention (unchanged)
    flash_mma_kernel<<<dim3(16, 64), 256, FL_SMEM>>>(
        qrh, qrl, khi, klo, vhi, vlo, ahi, alo);

    // Output projection (256-row tiles)
    gemm_mma_kernel<<<dim3(16, 16), 512, GEMM_SMEM>>>(
        ahi, alo, woh, wol, out, 4096, 2048, 2048);
}